// round 1
// baseline (speedup 1.0000x reference)
#include <cuda_runtime.h>
#include <cuda_bf16.h>
#include <math.h>

// Problem constants
#define DD      256      // embedding dim
#define KCODES  8192     // num embeddings
#define BATCH   8
#define HW      1024     // 32*32
#define NTOK    8192     // BATCH*HW

// Output layout (flattened return tuple, in order)
#define OUT_Q     0
#define Q_ELEMS   2097152          // 8*256*32*32
#define OUT_LOSS  2097152
#define OUT_PERP  2097153
#define OUT_IDX   2097154          // 8192
#define OUT_DW    2105346          // 256*8192
#define OUT_CS    4202498          // 8192

// GEMM tiling
#define MT     64                  // tokens per block
#define NT     128                 // codes per inner tile
#define DCH    16                  // d chunk
#define SPLITS 4
#define CODES_PER_SPLIT (KCODES / SPLITS)   // 2048
#define SMEM_BYTES ((DD * MT + DCH * NT) * 4)  // 64KB z-tile + 8KB e-chunk = 73728

// Scratch (device globals: no allocation allowed)
__device__ float               g_e2[KCODES];
__device__ float               g_sx2[NTOK];
__device__ unsigned long long  g_best[NTOK];
__device__ int                 g_idx[NTOK];
__device__ double              g_loss;

// ---------------------------------------------------------------------------
// K0: zero dw + cluster_size regions of out, g_best, g_loss
// ---------------------------------------------------------------------------
__global__ void k_init(float* __restrict__ out) {
    int i = blockIdx.x * blockDim.x + threadIdx.x;
    const int nz = 2097152 + 8192;   // dw + cs contiguous starting at OUT_DW
    if (i < nz)    out[OUT_DW + i] = 0.0f;
    if (i < NTOK)  g_best[i] = 0ull;
    if (i == 0)    g_loss = 0.0;
}

// ---------------------------------------------------------------------------
// K0b: per-code |e|^2 and per-token |x|^2
// ---------------------------------------------------------------------------
__global__ void k_norms(const float* __restrict__ z, const float* __restrict__ E) {
    int t = blockIdx.x * 256 + threadIdx.x;
    if (t < KCODES) {
        float s = 0.0f;
        #pragma unroll 8
        for (int d = 0; d < DD; d++) {
            float v = E[d * KCODES + t];   // coalesced across warp
            s += v * v;
        }
        g_e2[t] = s;
    } else if (t < KCODES + NTOK) {
        int n = t - KCODES;
        int b = n / HW, hw = n % HW;
        const float* zp = z + b * DD * HW + hw;
        float s = 0.0f;
        #pragma unroll 8
        for (int d = 0; d < DD; d++) {
            float v = zp[d * HW];          // coalesced across warp
            s += v * v;
        }
        g_sx2[n] = s;
    }
}

// ---------------------------------------------------------------------------
// K1: fused distance-GEMM + argmin.
// Block: 256 threads (16 tx = codes, 16 ty = tokens). Thread tile 4 tok x 8 codes.
// Block tile: 64 tokens x 128 codes, full D=256 in smem for z, E streamed in
// 16-deep d-chunks with register prefetch. Per-thread running argmin across
// all code tiles of this split; one atomicMax per (token, block) at the end.
// ---------------------------------------------------------------------------
__global__ void __launch_bounds__(256, 2)
k_argmin(const float* __restrict__ z, const float* __restrict__ E) {
    extern __shared__ float smem[];
    float* sz = smem;            // [256][64]  z-tile, d-major
    float* se = smem + DD * MT;  // [16][128]  e-chunk

    const int tid = threadIdx.x;
    const int tx  = tid & 15;    // code dim
    const int ty  = tid >> 4;    // token dim

    const int m0  = blockIdx.x * MT;
    const int b   = m0 / HW;
    const int hw0 = m0 % HW;
    const float* zb = z + b * DD * HW + hw0;

    // Load z tile: sz[d*64 + t] = z[b, d, hw0+t]   (coalesced, 64 floats/row)
    #pragma unroll 4
    for (int i = tid; i < DD * MT; i += 256) {
        int d = i >> 6, t = i & 63;
        sz[i] = zb[d * HW + t];
    }
    __syncthreads();

    float sx2[4];
    #pragma unroll
    for (int i = 0; i < 4; i++) sx2[i] = g_sx2[m0 + ty * 4 + i];

    unsigned long long best[4] = {0ull, 0ull, 0ull, 0ull};

    const int k0base = blockIdx.y * CODES_PER_SPLIT;

    for (int ct = 0; ct < CODES_PER_SPLIT; ct += NT) {
        const int k0 = k0base + ct;

        float acc[4][8];
        #pragma unroll
        for (int i = 0; i < 4; i++)
            #pragma unroll
            for (int j = 0; j < 8; j++) acc[i][j] = 0.0f;

        // Register-prefetch chunk 0: 2048 floats = 512 float4, 2 per thread.
        // float4 index q: d_local = q>>5, k_local = (q&31)*4
        float4 pf0, pf1;
        {
            int q0 = tid, q1 = tid + 256;
            pf0 = *(const float4*)&E[(q0 >> 5) * KCODES + k0 + ((q0 & 31) << 2)];
            pf1 = *(const float4*)&E[(q1 >> 5) * KCODES + k0 + ((q1 & 31) << 2)];
        }

        for (int c = 0; c < DD / DCH; c++) {
            __syncthreads();                      // se free (prev chunk consumed)
            ((float4*)se)[tid]        = pf0;
            ((float4*)se)[tid + 256]  = pf1;
            __syncthreads();                      // se ready

            if (c < DD / DCH - 1) {               // prefetch next chunk
                int q0 = tid, q1 = tid + 256;
                int dg0 = (c + 1) * DCH + (q0 >> 5);
                int dg1 = (c + 1) * DCH + (q1 >> 5);
                pf0 = *(const float4*)&E[dg0 * KCODES + k0 + ((q0 & 31) << 2)];
                pf1 = *(const float4*)&E[dg1 * KCODES + k0 + ((q1 & 31) << 2)];
            }

            #pragma unroll
            for (int dd = 0; dd < DCH; dd++) {
                const int d = c * DCH + dd;
                float4 ra  = *(const float4*)&sz[d * 64 + ty * 4];
                float4 rb0 = *(const float4*)&se[dd * NT + tx * 8];
                float4 rb1 = *(const float4*)&se[dd * NT + tx * 8 + 4];
                float av[4] = {ra.x, ra.y, ra.z, ra.w};
                float bv[8] = {rb0.x, rb0.y, rb0.z, rb0.w,
                               rb1.x, rb1.y, rb1.z, rb1.w};
                #pragma unroll
                for (int i = 0; i < 4; i++)
                    #pragma unroll
                    for (int j = 0; j < 8; j++)
                        acc[i][j] += av[i] * bv[j];
            }
        }

        // Epilogue: distances in the reference's fp32 form (|x|^2 - 2xe) + |e|^2,
        // so near-ties bucket exactly like the reference; argmin, tie -> lowest k.
        #pragma unroll
        for (int j = 0; j < 8; j++) {
            const int k = k0 + tx * 8 + j;
            const float e2 = g_e2[k];
            #pragma unroll
            for (int i = 0; i < 4; i++) {
                float dist = (sx2[i] - 2.0f * acc[i][j]) + e2;
                unsigned int u = __float_as_uint(dist);
                unsigned int m = (u & 0x80000000u) ? ~u : (u | 0x80000000u); // order-preserving
                unsigned int hi = ~m;                                        // min -> max key
                unsigned long long key =
                    ((unsigned long long)hi << 32) | (unsigned int)(KCODES - 1 - k);
                if (key > best[i]) best[i] = key;
            }
        }
    }

    // Reduce over tx (lanes xor 1..8 touch only the tx bits), then one atomic/token.
    #pragma unroll
    for (int i = 0; i < 4; i++) {
        unsigned long long v = best[i];
        #pragma unroll
        for (int s = 8; s >= 1; s >>= 1) {
            unsigned long long o = __shfl_xor_sync(0xffffffffu, v, s);
            if (o > v) v = o;
        }
        if (tx == 0) atomicMax(&g_best[m0 + ty * 4 + i], v);
    }
}

// ---------------------------------------------------------------------------
// K2a: decode winners -> indices (as float), cluster_size
// ---------------------------------------------------------------------------
__global__ void k_assign(float* __restrict__ out) {
    int n = blockIdx.x * 256 + threadIdx.x;
    if (n >= NTOK) return;
    unsigned long long key = g_best[n];
    int idx = (KCODES - 1) - (int)(unsigned int)(key & 0xffffffffu);
    g_idx[n] = idx;
    out[OUT_IDX + n] = (float)idx;
    atomicAdd(&out[OUT_CS + idx], 1.0f);
}

// ---------------------------------------------------------------------------
// K2b: gather quantized (NCHW), scatter dw, accumulate loss
// grid (hw_tiles=32, d_tiles=32, b=8), block 256 = 32(hw) x 8(d)
// ---------------------------------------------------------------------------
__global__ void k_scatter(const float* __restrict__ z, const float* __restrict__ E,
                          float* __restrict__ out) {
    int tx = threadIdx.x & 31;          // hw
    int ty = threadIdx.x >> 5;          // d
    int hw = blockIdx.x * 32 + tx;
    int d  = blockIdx.y * 8 + ty;
    int b  = blockIdx.z;

    int n   = b * HW + hw;
    int idx = g_idx[n];
    float q  = E[d * KCODES + idx];
    int   zi = (b * DD + d) * HW + hw;
    float zv = z[zi];
    out[OUT_Q + zi] = q;
    float diff = q - zv;
    atomicAdd(&out[OUT_DW + d * KCODES + idx], zv);

    __shared__ float red[256];
    red[threadIdx.x] = diff * diff;
    __syncthreads();
    #pragma unroll
    for (int s = 128; s > 0; s >>= 1) {
        if (threadIdx.x < s) red[threadIdx.x] += red[threadIdx.x + s];
        __syncthreads();
    }
    if (threadIdx.x == 0) atomicAdd(&g_loss, (double)red[0]);
}

// ---------------------------------------------------------------------------
// K3: loss + perplexity
// ---------------------------------------------------------------------------
__global__ void k_final(float* __restrict__ out) {
    __shared__ float red[256];
    int t = threadIdx.x;
    float s = 0.0f;
    for (int k = t; k < KCODES; k += 256) {
        float p = out[OUT_CS + k] * (1.0f / 8192.0f);
        s += p * logf(p + 1e-10f);
    }
    red[t] = s;
    __syncthreads();
    #pragma unroll
    for (int st = 128; st > 0; st >>= 1) {
        if (t < st) red[t] += red[t + st];
        __syncthreads();
    }
    if (t == 0) {
        out[OUT_PERP] = expf(-red[0]);
        out[OUT_LOSS] = (float)(0.25 * g_loss / 2097152.0);
    }
}

// ---------------------------------------------------------------------------
extern "C" void kernel_launch(void* const* d_in, const int* in_sizes, int n_in,
                              void* d_out, int out_size) {
    const float* z = (const float*)d_in[0];         // [8,256,32,32]
    const float* E = (const float*)d_in[1];         // [256,8192]
    float* out = (float*)d_out;

    cudaFuncSetAttribute(k_argmin, cudaFuncAttributeMaxDynamicSharedMemorySize,
                         SMEM_BYTES);

    k_init   <<< (2097152 + 8192 + 255) / 256, 256 >>>(out);
    k_norms  <<< (KCODES + NTOK + 255) / 256, 256 >>>(z, E);
    k_argmin <<< dim3(NTOK / MT, SPLITS), 256, SMEM_BYTES >>>(z, E);
    k_assign <<< NTOK / 256, 256 >>>(out);
    k_scatter<<< dim3(HW / 32, DD / 8, BATCH), 256 >>>(z, E, out);
    k_final  <<< 1, 256 >>>(out);
}

// round 2
// speedup vs baseline: 1.7529x; 1.7529x over previous
#include <cuda_runtime.h>
#include <cuda_bf16.h>
#include <math.h>

// Problem constants
#define DD      256      // embedding dim
#define KCODES  8192     // num embeddings
#define BATCH   8
#define HW      1024     // 32*32
#define NTOK    8192     // BATCH*HW

// Output layout (flattened return tuple, in order)
#define OUT_Q     0
#define OUT_LOSS  2097152
#define OUT_PERP  2097153
#define OUT_IDX   2097154          // 8192
#define OUT_DW    2105346          // 256*8192
#define OUT_CS    4202498          // 8192

// GEMM tiling
#define MT     128                 // tokens per block
#define NT     128                 // codes per inner tile
#define DCH    16                  // d chunk
#define SPLITS 16
#define CODES_PER_SPLIT (KCODES / SPLITS)          // 512
#define SMEM_BYTES ((DD * MT + DCH * NT) * 4)      // 128KB z-tile + 8KB e-chunk

typedef unsigned long long ull;

// Scratch (device globals: no allocation allowed)
__device__ float  g_e2[KCODES];
__device__ float  g_sx2[NTOK];
__device__ ull    g_best[NTOK];
__device__ int    g_idx[NTOK];
__device__ double g_loss;

// ---- packed fp32x2 helpers (Blackwell) -------------------------------------
__device__ __forceinline__ ull f32x2_pack_dup(float f) {
    ull r;
    unsigned int u = __float_as_uint(f);
    asm("mov.b64 %0, {%1, %1};" : "=l"(r) : "r"(u));
    return r;
}
__device__ __forceinline__ ull f32x2_fma(ull a, ull b, ull c) {
    ull d;
    asm("fma.rn.f32x2 %0, %1, %2, %3;" : "=l"(d) : "l"(a), "l"(b), "l"(c));
    return d;
}
__device__ __forceinline__ void f32x2_unpack(ull v, float& lo, float& hi) {
    unsigned int l, h;
    asm("mov.b64 {%0, %1}, %2;" : "=r"(l), "=r"(h) : "l"(v));
    lo = __uint_as_float(l);
    hi = __uint_as_float(h);
}

// ---------------------------------------------------------------------------
// K0: zero dw + cluster_size regions of out, g_best, g_loss
// ---------------------------------------------------------------------------
__global__ void k_init(float* __restrict__ out) {
    int i = blockIdx.x * blockDim.x + threadIdx.x;
    const int nz = 2097152 + 8192;   // dw + cs contiguous starting at OUT_DW
    if (i < nz)    out[OUT_DW + i] = 0.0f;
    if (i < NTOK)  g_best[i] = 0ull;
    if (i == 0)    g_loss = 0.0;
}

// ---------------------------------------------------------------------------
// K0b: per-code |e|^2 and per-token |x|^2
// ---------------------------------------------------------------------------
__global__ void k_norms(const float* __restrict__ z, const float* __restrict__ E) {
    int t = blockIdx.x * 256 + threadIdx.x;
    if (t < KCODES) {
        float s = 0.0f;
        #pragma unroll 8
        for (int d = 0; d < DD; d++) {
            float v = E[d * KCODES + t];   // coalesced across warp
            s += v * v;
        }
        g_e2[t] = s;
    } else if (t < KCODES + NTOK) {
        int n = t - KCODES;
        int b = n / HW, hw = n % HW;
        const float* zp = z + b * DD * HW + hw;
        float s = 0.0f;
        #pragma unroll 8
        for (int d = 0; d < DD; d++) {
            float v = zp[d * HW];          // coalesced across warp
            s += v * v;
        }
        g_sx2[n] = s;
    }
}

// ---------------------------------------------------------------------------
// K1: fused distance-GEMM + argmin, packed f32x2 math path.
// Block: 256 threads (16 tx = codes, 16 ty = tokens). Thread tile 8 tok x 8
// codes (4 code-pairs in 64-bit accumulators). Block tile 128 tok x 128 codes,
// z tile (128KB) resident in smem, E streamed in 16-deep d-chunks with
// register prefetch. Packed fma.rn.f32x2 rounds each half identically to
// scalar FFMA, so distances are bit-identical to the round-1 kernel.
// ---------------------------------------------------------------------------
__global__ void __launch_bounds__(256, 1)
k_argmin(const float* __restrict__ z, const float* __restrict__ E) {
    extern __shared__ float smem[];
    float* sz = smem;            // [256][128]  z-tile, d-major
    float* se = smem + DD * MT;  // [16][128]   e-chunk

    const int tid = threadIdx.x;
    const int tx  = tid & 15;    // code dim (8 codes = 4 pairs each)
    const int ty  = tid >> 4;    // token dim (8 tokens each)

    const int m0  = blockIdx.x * MT;
    const int b   = m0 / HW;
    const int hw0 = m0 % HW;
    const float* zb = z + b * DD * HW + hw0;

    // Load z tile: sz[d*128 + t] = z[b, d, hw0+t]  (float4, fully coalesced)
    #pragma unroll 4
    for (int i = tid; i < DD * MT / 4; i += 256) {
        int d = i >> 5, t4 = i & 31;
        ((float4*)sz)[i] = *(const float4*)&zb[d * HW + t4 * 4];
    }
    __syncthreads();

    float sx2[8];
    #pragma unroll
    for (int i = 0; i < 8; i++) sx2[i] = g_sx2[m0 + ty * 8 + i];

    ull best[8];
    #pragma unroll
    for (int i = 0; i < 8; i++) best[i] = 0ull;

    const int k0base = blockIdx.y * CODES_PER_SPLIT;

    for (int ct = 0; ct < CODES_PER_SPLIT; ct += NT) {
        const int k0 = k0base + ct;

        ull acc[8][4];
        #pragma unroll
        for (int i = 0; i < 8; i++)
            #pragma unroll
            for (int j = 0; j < 4; j++) acc[i][j] = 0ull;

        // Register-prefetch chunk 0: 2048 floats = 512 float4, 2 per thread.
        float4 pf0, pf1;
        {
            int q0 = tid, q1 = tid + 256;
            pf0 = *(const float4*)&E[(q0 >> 5) * KCODES + k0 + ((q0 & 31) << 2)];
            pf1 = *(const float4*)&E[(q1 >> 5) * KCODES + k0 + ((q1 & 31) << 2)];
        }

        for (int c = 0; c < DD / DCH; c++) {
            __syncthreads();                      // se free (prev chunk consumed)
            ((float4*)se)[tid]        = pf0;
            ((float4*)se)[tid + 256]  = pf1;
            __syncthreads();                      // se ready

            if (c < DD / DCH - 1) {               // prefetch next chunk
                int q0 = tid, q1 = tid + 256;
                int dg0 = (c + 1) * DCH + (q0 >> 5);
                int dg1 = (c + 1) * DCH + (q1 >> 5);
                pf0 = *(const float4*)&E[dg0 * KCODES + k0 + ((q0 & 31) << 2)];
                pf1 = *(const float4*)&E[dg1 * KCODES + k0 + ((q1 & 31) << 2)];
            }

            #pragma unroll
            for (int dd = 0; dd < DCH; dd++) {
                const int d = c * DCH + dd;
                // a: 8 token values (broadcast across tx)
                float4 ra0 = *(const float4*)&sz[d * MT + ty * 8];
                float4 ra1 = *(const float4*)&sz[d * MT + ty * 8 + 4];
                // b: 8 code values = 4 f32x2 pairs, loaded directly as u64 pairs
                ulonglong2 rb0 = *(const ulonglong2*)&se[dd * NT + tx * 8];
                ulonglong2 rb1 = *(const ulonglong2*)&se[dd * NT + tx * 8 + 4];
                ull bp[4] = {rb0.x, rb0.y, rb1.x, rb1.y};
                float av[8] = {ra0.x, ra0.y, ra0.z, ra0.w,
                               ra1.x, ra1.y, ra1.z, ra1.w};
                ull ap[8];
                #pragma unroll
                for (int i = 0; i < 8; i++) ap[i] = f32x2_pack_dup(av[i]);
                #pragma unroll
                for (int i = 0; i < 8; i++)
                    #pragma unroll
                    for (int j = 0; j < 4; j++)
                        acc[i][j] = f32x2_fma(ap[i], bp[j], acc[i][j]);
            }
        }

        // Epilogue: distances in the reference's fp32 form (|x|^2 - 2xe) + |e|^2;
        // argmin with tie-break to lowest code index, as packed order keys.
        #pragma unroll
        for (int jp = 0; jp < 4; jp++) {
            const int klo = k0 + tx * 8 + jp * 2;
            const float e2lo = g_e2[klo];
            const float e2hi = g_e2[klo + 1];
            #pragma unroll
            for (int i = 0; i < 8; i++) {
                float dlo, dhi;
                f32x2_unpack(acc[i][jp], dlo, dhi);
                {
                    float dist = (sx2[i] - 2.0f * dlo) + e2lo;
                    unsigned int u = __float_as_uint(dist);
                    unsigned int m = (u & 0x80000000u) ? ~u : (u | 0x80000000u);
                    ull key = ((ull)(~m) << 32) | (unsigned int)(KCODES - 1 - klo);
                    if (key > best[i]) best[i] = key;
                }
                {
                    float dist = (sx2[i] - 2.0f * dhi) + e2hi;
                    unsigned int u = __float_as_uint(dist);
                    unsigned int m = (u & 0x80000000u) ? ~u : (u | 0x80000000u);
                    ull key = ((ull)(~m) << 32) | (unsigned int)(KCODES - 1 - (klo + 1));
                    if (key > best[i]) best[i] = key;
                }
            }
        }
    }

    // Reduce over tx (lanes xor 1..8 stay inside the 16-lane tx group),
    // then one atomicMax per token.
    #pragma unroll
    for (int i = 0; i < 8; i++) {
        ull v = best[i];
        #pragma unroll
        for (int s = 8; s >= 1; s >>= 1) {
            ull o = __shfl_xor_sync(0xffffffffu, v, s);
            if (o > v) v = o;
        }
        if (tx == 0) atomicMax(&g_best[m0 + ty * 8 + i], v);
    }
}

// ---------------------------------------------------------------------------
// K2a: decode winners -> indices (as float), cluster_size
// ---------------------------------------------------------------------------
__global__ void k_assign(float* __restrict__ out) {
    int n = blockIdx.x * 256 + threadIdx.x;
    if (n >= NTOK) return;
    ull key = g_best[n];
    int idx = (KCODES - 1) - (int)(unsigned int)(key & 0xffffffffu);
    g_idx[n] = idx;
    out[OUT_IDX + n] = (float)idx;
    atomicAdd(&out[OUT_CS + idx], 1.0f);
}

// ---------------------------------------------------------------------------
// K2b: gather quantized (NCHW), scatter dw, accumulate loss
// grid (hw_tiles=32, d_tiles=32, b=8), block 256 = 32(hw) x 8(d)
// ---------------------------------------------------------------------------
__global__ void k_scatter(const float* __restrict__ z, const float* __restrict__ E,
                          float* __restrict__ out) {
    int tx = threadIdx.x & 31;          // hw
    int ty = threadIdx.x >> 5;          // d
    int hw = blockIdx.x * 32 + tx;
    int d  = blockIdx.y * 8 + ty;
    int b  = blockIdx.z;

    int n   = b * HW + hw;
    int idx = g_idx[n];
    float q  = E[d * KCODES + idx];
    int   zi = (b * DD + d) * HW + hw;
    float zv = z[zi];
    out[OUT_Q + zi] = q;
    float diff = q - zv;
    atomicAdd(&out[OUT_DW + d * KCODES + idx], zv);

    __shared__ float red[256];
    red[threadIdx.x] = diff * diff;
    __syncthreads();
    #pragma unroll
    for (int s = 128; s > 0; s >>= 1) {
        if (threadIdx.x < s) red[threadIdx.x] += red[threadIdx.x + s];
        __syncthreads();
    }
    if (threadIdx.x == 0) atomicAdd(&g_loss, (double)red[0]);
}

// ---------------------------------------------------------------------------
// K3: loss + perplexity
// ---------------------------------------------------------------------------
__global__ void k_final(float* __restrict__ out) {
    __shared__ float red[256];
    int t = threadIdx.x;
    float s = 0.0f;
    for (int k = t; k < KCODES; k += 256) {
        float p = out[OUT_CS + k] * (1.0f / 8192.0f);
        s += p * logf(p + 1e-10f);
    }
    red[t] = s;
    __syncthreads();
    #pragma unroll
    for (int st = 128; st > 0; st >>= 1) {
        if (t < st) red[t] += red[t + st];
        __syncthreads();
    }
    if (t == 0) {
        out[OUT_PERP] = expf(-red[0]);
        out[OUT_LOSS] = (float)(0.25 * g_loss / 2097152.0);
    }
}

// ---------------------------------------------------------------------------
extern "C" void kernel_launch(void* const* d_in, const int* in_sizes, int n_in,
                              void* d_out, int out_size) {
    const float* z = (const float*)d_in[0];         // [8,256,32,32]
    const float* E = (const float*)d_in[1];         // [256,8192]
    float* out = (float*)d_out;

    cudaFuncSetAttribute(k_argmin, cudaFuncAttributeMaxDynamicSharedMemorySize,
                         SMEM_BYTES);

    k_init   <<< (2097152 + 8192 + 255) / 256, 256 >>>(out);
    k_norms  <<< (KCODES + NTOK + 255) / 256, 256 >>>(z, E);
    k_argmin <<< dim3(NTOK / MT, SPLITS), 256, SMEM_BYTES >>>(z, E);
    k_assign <<< NTOK / 256, 256 >>>(out);
    k_scatter<<< dim3(HW / 32, DD / 8, BATCH), 256 >>>(z, E, out);
    k_final  <<< 1, 256 >>>(out);
}

// round 4
// speedup vs baseline: 2.6760x; 1.5266x over previous
#include <cuda_runtime.h>
#include <cuda_bf16.h>
#include <math.h>

// Problem constants
#define DD      256
#define KCODES  8192
#define BATCH   8
#define HW      1024
#define NTOK    8192

// Output layout (flattened return tuple, in order)
#define OUT_Q     0
#define OUT_LOSS  2097152
#define OUT_PERP  2097153
#define OUT_IDX   2097154
#define OUT_DW    2105346
#define OUT_CS    4202498

// GEMM config: C[8192 tok, 8192 codes] = A[.,768] * B[.,768]^T  (bf16x3 split)
#define KTOT    768
#define MTILE   256
#define NTILE   128
#define KS      64
#define NSTAGES 12                    // 768/64
#define NSPLITS (KCODES / NTILE)      // 64
#define SMEM_DYN 98304                // A: 2*32KB, B: 2*16KB

typedef unsigned long long ull;
typedef unsigned int uint;

// ---------------- device scratch (no allocation allowed) --------------------
__device__ __nv_bfloat16 g_A[NTOK   * KTOT];  // [tok ][xh(256)|xh(256)|xl(256)]
__device__ __nv_bfloat16 g_B[KCODES * KTOT];  // [code][eh(256)|el(256)|eh(256)]
__device__ float  g_e2[KCODES];
__device__ float  g_sx2[NTOK];
__device__ ull    g_top1[NSPLITS * NTOK];     // [split][token]
__device__ ull    g_top2[NSPLITS * NTOK];
__device__ int    g_idx[NTOK];
__device__ double g_loss;

// ---------------- PTX helpers (all plain-sm_100 legal) ----------------------
__device__ __forceinline__ uint smem_u32(const void* p) {
    uint a;
    asm("{ .reg .u64 t; cvta.to.shared.u64 t, %1; cvt.u32.u64 %0, t; }"
        : "=r"(a) : "l"(p));
    return a;
}
#define CP16(dst, src) \
    asm volatile("cp.async.cg.shared.global [%0], [%1], 16;" :: "r"(dst), "l"(src))
#define CP_COMMIT() asm volatile("cp.async.commit_group;")
#define CP_WAIT(n)  asm volatile("cp.async.wait_group %0;" :: "n"(n))

#define LDSM4(r0, r1, r2, r3, a) \
    asm volatile("ldmatrix.sync.aligned.m8n8.x4.shared.b16 {%0,%1,%2,%3}, [%4];" \
        : "=r"(r0), "=r"(r1), "=r"(r2), "=r"(r3) : "r"(a))

#define MMA16816(c, a, b) \
    asm volatile("mma.sync.aligned.m16n8k16.row.col.f32.bf16.bf16.f32 " \
        "{%0,%1,%2,%3}, {%4,%5,%6,%7}, {%8,%9}, {%0,%1,%2,%3};" \
        : "+f"((c)[0]), "+f"((c)[1]), "+f"((c)[2]), "+f"((c)[3]) \
        : "r"((a)[0]), "r"((a)[1]), "r"((a)[2]), "r"((a)[3]), \
          "r"((b)[0]), "r"((b)[1]))

__device__ __forceinline__ ull umax(ull a, ull b) { return a > b ? a : b; }
__device__ __forceinline__ ull umin(ull a, ull b) { return a < b ? a : b; }

// ---------------------------------------------------------------------------
// K0: zero dw + cluster_size region, g_loss
// ---------------------------------------------------------------------------
__global__ void k_init(float* __restrict__ out) {
    int i = blockIdx.x * blockDim.x + threadIdx.x;
    const int nz = 2097152 + 8192;
    if (i < nz)  out[OUT_DW + i] = 0.0f;
    if (i == 0)  g_loss = 0.0;
}

// ---------------------------------------------------------------------------
// K0b: per-code |e|^2 and per-token |x|^2 (exact fp32)
// ---------------------------------------------------------------------------
__global__ void k_norms(const float* __restrict__ z, const float* __restrict__ E) {
    int t = blockIdx.x * 256 + threadIdx.x;
    if (t < KCODES) {
        float s = 0.0f;
        #pragma unroll 8
        for (int d = 0; d < DD; d++) { float v = E[d * KCODES + t]; s += v * v; }
        g_e2[t] = s;
    } else if (t < KCODES + NTOK) {
        int n = t - KCODES;
        int b = n / HW, hw = n % HW;
        const float* zp = z + b * DD * HW + hw;
        float s = 0.0f;
        #pragma unroll 8
        for (int d = 0; d < DD; d++) { float v = zp[d * HW]; s += v * v; }
        g_sx2[n] = s;
    }
}

// ---------------------------------------------------------------------------
// K_prep: transpose + bf16 hi/lo split. Blocks 0..255: z -> g_A (32 tok each).
// Blocks 256..511: E -> g_B (32 codes each).
//   A row: [xh | xh | xl]      B row: [eh | el | eh]
// ---------------------------------------------------------------------------
__global__ void k_prep(const float* __restrict__ z, const float* __restrict__ E) {
    __shared__ float st[32 * 264];
    int tid = threadIdx.x;
    bool isB = blockIdx.x >= 256;
    int n0 = (isB ? (blockIdx.x - 256) : blockIdx.x) * 32;

    for (int i = tid; i < 32 * 256; i += 256) {
        int k = i >> 5, nl = i & 31;
        float v;
        if (isB) v = E[k * KCODES + n0 + nl];
        else {
            int b = n0 >> 10, hw0 = n0 & 1023;
            v = z[(b * DD + k) * HW + hw0 + nl];
        }
        st[nl * 264 + k] = v;
    }
    __syncthreads();

    __nv_bfloat16* dst = isB ? g_B : g_A;
    int nl = tid >> 3;
    int jb = (tid & 7) * 32;
    __nv_bfloat16* rowp = dst + (ull)(n0 + nl) * KTOT;
    #pragma unroll 8
    for (int j = 0; j < 32; j++) {
        float v = st[nl * 264 + jb + j];
        __nv_bfloat16 h = __float2bfloat16(v);
        __nv_bfloat16 l = __float2bfloat16(v - __bfloat162float(h));
        rowp[jb + j]       = h;
        rowp[256 + jb + j] = isB ? l : h;
        rowp[512 + jb + j] = isB ? h : l;
    }
}

// ---------------------------------------------------------------------------
// K1: HMMA bf16 distance GEMM fused with per-token top-2.
// Grid (32 token-tiles, 64 code-tiles). 256 threads = 8 warps (4m x 2n),
// warp tile 64x64, cp.async double-buffered K stages of 64, XOR-swizzled smem.
// ---------------------------------------------------------------------------
__global__ void __launch_bounds__(256, 1)
k_mma() {
    extern __shared__ char smem[];
    const uint sb  = smem_u32(smem);
    const uint sA  = sb;            // 2 x 32KB
    const uint sB  = sb + 65536;    // 2 x 16KB

    const int tid  = threadIdx.x;
    const int lane = tid & 31;
    const int wid  = tid >> 5;
    const int wm   = wid & 3;       // m warp (4)
    const int wn   = wid >> 2;      // n warp (2)

    const int m0   = blockIdx.x * MTILE;
    const int nblk = blockIdx.y;
    const int n0   = nblk * NTILE;

    const __nv_bfloat16* gA = g_A + (ull)m0 * KTOT;
    const __nv_bfloat16* gB = g_B + (ull)n0 * KTOT;

    float c[4][8][4];
    #pragma unroll
    for (int i = 0; i < 4; i++)
        #pragma unroll
        for (int j = 0; j < 8; j++)
            #pragma unroll
            for (int r = 0; r < 4; r++) c[i][j][r] = 0.0f;

    // ldmatrix per-thread row bases
    const int rowA = wm * 64 + (lane & 7) + ((lane >> 3) & 1) * 8;  // + i*16
    const int sxA  = rowA & 7;
    const int chA  = (lane >> 4);          // k half select
    const int rowB = wn * 64 + (lane & 7) + ((lane >> 4) << 3);     // + nb*16
    const int sxB  = rowB & 7;
    const int chB  = (lane >> 3) & 1;

    // stage issuer
    auto issue = [&](int s) {
        const int kb = s * KS;
        const uint bufA = sA + (uint)(s & 1) * 32768u;
        const uint bufB = sB + (uint)(s & 1) * 16384u;
        #pragma unroll
        for (int i = 0; i < 8; i++) {
            int idx = i * 256 + tid;
            int row = idx >> 3, ch = idx & 7;
            uint dst = bufA + (uint)row * 128u + (uint)((ch ^ (row & 7)) << 4);
            CP16(dst, gA + (ull)row * KTOT + kb + ch * 8);
        }
        #pragma unroll
        for (int i = 0; i < 4; i++) {
            int idx = i * 256 + tid;
            int row = idx >> 3, ch = idx & 7;
            uint dst = bufB + (uint)row * 128u + (uint)((ch ^ (row & 7)) << 4);
            CP16(dst, gB + (ull)row * KTOT + kb + ch * 8);
        }
        CP_COMMIT();
    };

    issue(0);
    issue(1);

    for (int s = 0; s < NSTAGES; s++) {
        if (s < NSTAGES - 1) { CP_WAIT(1); } else { CP_WAIT(0); }
        __syncthreads();

        const uint bufA = sA + (uint)(s & 1) * 32768u;
        const uint bufB = sB + (uint)(s & 1) * 16384u;

        #pragma unroll
        for (int ks = 0; ks < 4; ks++) {
            uint a[4][4];
            #pragma unroll
            for (int i = 0; i < 4; i++) {
                uint addr = bufA + (uint)(rowA + i * 16) * 128u
                          + (uint)(((ks * 2 + chA) ^ sxA) << 4);
                LDSM4(a[i][0], a[i][1], a[i][2], a[i][3], addr);
            }
            uint b[8][2];
            #pragma unroll
            for (int nb = 0; nb < 4; nb++) {
                uint r0, r1, r2, r3;
                uint addr = bufB + (uint)(rowB + nb * 16) * 128u
                          + (uint)(((ks * 2 + chB) ^ sxB) << 4);
                LDSM4(r0, r1, r2, r3, addr);
                b[nb * 2][0] = r0; b[nb * 2][1] = r1;
                b[nb * 2 + 1][0] = r2; b[nb * 2 + 1][1] = r3;
            }
            #pragma unroll
            for (int i = 0; i < 4; i++)
                #pragma unroll
                for (int j = 0; j < 8; j++)
                    MMA16816(c[i][j], a[i], b[j]);
        }
        __syncthreads();
        if (s + 2 < NSTAGES) issue(s + 2);
    }

    // ---------------- epilogue: dist + top-2, no atomics --------------------
    __syncthreads();                // all warps done with smem tiles
    ull* sred = (ull*)smem;         // [256 rows][2 warp_n][2]

    // hoist e2 for this thread's 16 n-columns
    float e2v[8][2];
    #pragma unroll
    for (int j = 0; j < 8; j++)
        #pragma unroll
        for (int q = 0; q < 2; q++)
            e2v[j][q] = g_e2[n0 + wn * 64 + j * 8 + (lane & 3) * 2 + q];

    #pragma unroll
    for (int i = 0; i < 4; i++) {
        #pragma unroll
        for (int h = 0; h < 2; h++) {
            const int m_local = wm * 64 + i * 16 + (lane >> 2) + h * 8;
            const float sx2 = g_sx2[m0 + m_local];
            ull b1 = 0ull, b2 = 0ull;
            #pragma unroll
            for (int j = 0; j < 8; j++) {
                #pragma unroll
                for (int q = 0; q < 2; q++) {
                    float dot  = c[i][j][h * 2 + q];
                    float dist = (sx2 - 2.0f * dot) + e2v[j][q];
                    const int n = n0 + wn * 64 + j * 8 + (lane & 3) * 2 + q;
                    uint u = __float_as_uint(dist);
                    uint m = (u & 0x80000000u) ? ~u : (u | 0x80000000u);
                    ull key = ((ull)(~m) << 32) | (uint)(KCODES - 1 - n);
                    if (key > b1)      { b2 = b1; b1 = key; }
                    else if (key > b2) { b2 = key; }
                }
            }
            // merge top-2 across the 4 lanes sharing this row (lane&3 group)
            #pragma unroll
            for (int sh = 1; sh <= 2; sh <<= 1) {
                ull o1 = __shfl_xor_sync(0xffffffffu, b1, sh);
                ull o2 = __shfl_xor_sync(0xffffffffu, b2, sh);
                ull n1 = umax(b1, o1);
                ull n2 = umax(umin(b1, o1), umax(b2, o2));
                b1 = n1; b2 = n2;
            }
            if ((lane & 3) == 0) {
                sred[(m_local * 2 + wn) * 2 + 0] = b1;
                sred[(m_local * 2 + wn) * 2 + 1] = b2;
            }
        }
    }
    __syncthreads();
    {
        const int row = tid;
        ull p1a = sred[(row * 2 + 0) * 2 + 0], p2a = sred[(row * 2 + 0) * 2 + 1];
        ull p1b = sred[(row * 2 + 1) * 2 + 0], p2b = sred[(row * 2 + 1) * 2 + 1];
        ull b1 = umax(p1a, p1b);
        ull b2 = umax(umin(p1a, p1b), umax(p2a, p2b));
        g_top1[nblk * NTOK + m0 + row] = b1;
        g_top2[nblk * NTOK + m0 + row] = b2;
    }
}

// ---------------------------------------------------------------------------
// K2a: merge per-split top-2, near-tie exact fp32 fixup, emit idx + cs
// ---------------------------------------------------------------------------
__device__ __forceinline__ float exact_dist(const float* z, const float* E,
                                            int n, int k) {
    int b = n >> 10, hw = n & 1023;
    const float* zp = z + b * DD * HW + hw;
    const float* ep = E + k;
    float dot = 0.0f;
    #pragma unroll 8
    for (int d = 0; d < DD; d++) dot = fmaf(zp[d * HW], ep[d * KCODES], dot);
    return (g_sx2[n] - 2.0f * dot) + g_e2[k];
}

__global__ void k_assign(const float* __restrict__ z, const float* __restrict__ E,
                         float* __restrict__ out) {
    int n = blockIdx.x * 256 + threadIdx.x;
    if (n >= NTOK) return;
    ull b1 = 0ull, b2 = 0ull;
    for (int s = 0; s < NSPLITS; s++) {
        ull t1 = g_top1[s * NTOK + n];
        ull t2 = g_top2[s * NTOK + n];
        if (t1 > b1)      { b2 = b1; b1 = t1; }
        else if (t1 > b2) { b2 = t1; }
        if (t2 > b2)      { b2 = t2; }
    }
    int i1 = (KCODES - 1) - (int)(uint)(b1 & 0xffffffffu);
    int i2 = (KCODES - 1) - (int)(uint)(b2 & 0xffffffffu);
    uint m1 = ~(uint)(b1 >> 32), m2 = ~(uint)(b2 >> 32);
    float d1 = __uint_as_float((m1 & 0x80000000u) ? (m1 & 0x7fffffffu) : ~m1);
    float d2 = __uint_as_float((m2 & 0x80000000u) ? (m2 & 0x7fffffffu) : ~m2);
    int idx = i1;
    if (d2 - d1 < 2e-4f) {   // near-tie: exact fp32 re-score (reference math)
        float e1  = exact_dist(z, E, n, i1);
        float e2x = exact_dist(z, E, n, i2);
        if (e2x < e1 || (e2x == e1 && i2 < i1)) idx = i2;
    }
    g_idx[n] = idx;
    out[OUT_IDX + n] = (float)idx;
    atomicAdd(&out[OUT_CS + idx], 1.0f);
}

// ---------------------------------------------------------------------------
// K2b: gather quantized (NCHW), scatter dw, accumulate loss
// ---------------------------------------------------------------------------
__global__ void k_scatter(const float* __restrict__ z, const float* __restrict__ E,
                          float* __restrict__ out) {
    int tx = threadIdx.x & 31;
    int ty = threadIdx.x >> 5;
    int hw = blockIdx.x * 32 + tx;
    int d  = blockIdx.y * 8 + ty;
    int b  = blockIdx.z;

    int n   = b * HW + hw;
    int idx = g_idx[n];
    float q  = E[d * KCODES + idx];
    int   zi = (b * DD + d) * HW + hw;
    float zv = z[zi];
    out[OUT_Q + zi] = q;
    float diff = q - zv;
    atomicAdd(&out[OUT_DW + d * KCODES + idx], zv);

    __shared__ float red[256];
    red[threadIdx.x] = diff * diff;
    __syncthreads();
    #pragma unroll
    for (int s = 128; s > 0; s >>= 1) {
        if (threadIdx.x < s) red[threadIdx.x] += red[threadIdx.x + s];
        __syncthreads();
    }
    if (threadIdx.x == 0) atomicAdd(&g_loss, (double)red[0]);
}

// ---------------------------------------------------------------------------
// K3: loss + perplexity
// ---------------------------------------------------------------------------
__global__ void k_final(float* __restrict__ out) {
    __shared__ float red[256];
    int t = threadIdx.x;
    float s = 0.0f;
    for (int k = t; k < KCODES; k += 256) {
        float p = out[OUT_CS + k] * (1.0f / 8192.0f);
        s += p * logf(p + 1e-10f);
    }
    red[t] = s;
    __syncthreads();
    #pragma unroll
    for (int st = 128; st > 0; st >>= 1) {
        if (t < st) red[t] += red[t + st];
        __syncthreads();
    }
    if (t == 0) {
        out[OUT_PERP] = expf(-red[0]);
        out[OUT_LOSS] = (float)(0.25 * g_loss / 2097152.0);
    }
}

// ---------------------------------------------------------------------------
extern "C" void kernel_launch(void* const* d_in, const int* in_sizes, int n_in,
                              void* d_out, int out_size) {
    const float* z = (const float*)d_in[0];         // [8,256,32,32]
    const float* E = (const float*)d_in[1];         // [256,8192]
    float* out = (float*)d_out;

    cudaFuncSetAttribute(k_mma, cudaFuncAttributeMaxDynamicSharedMemorySize,
                         SMEM_DYN);

    k_init   <<< (2097152 + 8192 + 255) / 256, 256 >>>(out);
    k_norms  <<< (KCODES + NTOK + 255) / 256, 256 >>>(z, E);
    k_prep   <<< 512, 256 >>>(z, E);
    k_mma    <<< dim3(NTOK / MTILE, NSPLITS), 256, SMEM_DYN >>>();
    k_assign <<< NTOK / 256, 256 >>>(z, E, out);
    k_scatter<<< dim3(HW / 32, DD / 8, BATCH), 256 >>>(z, E, out);
    k_final  <<< 1, 256 >>>(out);
}

// round 5
// speedup vs baseline: 2.7618x; 1.0321x over previous
#include <cuda_runtime.h>
#include <cuda_bf16.h>
#include <math.h>

// Problem constants
#define DD      256
#define KCODES  8192
#define BATCH   8
#define HW      1024
#define NTOK    8192

// Output layout (flattened return tuple, in order)
#define OUT_Q     0
#define OUT_LOSS  2097152
#define OUT_PERP  2097153
#define OUT_IDX   2097154
#define OUT_DW    2105346
#define OUT_CS    4202498

// GEMM config: C[8192 tok, 8192 codes] = A[.,768] * B[.,768]^T  (bf16x3 split)
#define KTOT    768
#define MTILE   256
#define NTILE   128
#define KS      64
#define NSTAGES 12                    // 768/64
#define NPIPE   4                     // cp.async pipeline depth
#define NSPLITS (KCODES / NTILE)      // 64
#define ABYTES  32768                 // per-stage A buffer
#define BBYTES  16384                 // per-stage B buffer
#define SMEM_DYN (NPIPE * (ABYTES + BBYTES))   // 192KB

typedef unsigned long long ull;
typedef unsigned int uint;

// ---------------- device scratch (no allocation allowed) --------------------
__device__ __nv_bfloat16 g_A[NTOK   * KTOT];  // [tok ][xh(256)|xh(256)|xl(256)]
__device__ __nv_bfloat16 g_B[KCODES * KTOT];  // [code][eh(256)|el(256)|eh(256)]
__device__ float  g_e2[KCODES];
__device__ float  g_sx2[NTOK];
__device__ ull    g_top1[NSPLITS * NTOK];     // [split][token]
__device__ ull    g_top2[NSPLITS * NTOK];
__device__ int    g_idx[NTOK];
__device__ double g_loss;

// ---------------- PTX helpers (all plain-sm_100 legal) ----------------------
__device__ __forceinline__ uint smem_u32(const void* p) {
    uint a;
    asm("{ .reg .u64 t; cvta.to.shared.u64 t, %1; cvt.u32.u64 %0, t; }"
        : "=r"(a) : "l"(p));
    return a;
}
#define CP16(dst, src) \
    asm volatile("cp.async.cg.shared.global [%0], [%1], 16;" :: "r"(dst), "l"(src))
#define CP_COMMIT() asm volatile("cp.async.commit_group;")
#define CP_WAIT(n)  asm volatile("cp.async.wait_group %0;" :: "n"(n))

#define LDSM4(r0, r1, r2, r3, a) \
    asm volatile("ldmatrix.sync.aligned.m8n8.x4.shared.b16 {%0,%1,%2,%3}, [%4];" \
        : "=r"(r0), "=r"(r1), "=r"(r2), "=r"(r3) : "r"(a))

#define MMA16816(c, a, b) \
    asm volatile("mma.sync.aligned.m16n8k16.row.col.f32.bf16.bf16.f32 " \
        "{%0,%1,%2,%3}, {%4,%5,%6,%7}, {%8,%9}, {%0,%1,%2,%3};" \
        : "+f"((c)[0]), "+f"((c)[1]), "+f"((c)[2]), "+f"((c)[3]) \
        : "r"((a)[0]), "r"((a)[1]), "r"((a)[2]), "r"((a)[3]), \
          "r"((b)[0]), "r"((b)[1]))

__device__ __forceinline__ ull umax(ull a, ull b) { return a > b ? a : b; }
__device__ __forceinline__ ull umin(ull a, ull b) { return a < b ? a : b; }

// ---------------------------------------------------------------------------
// K0: zero dw + cluster_size region, g_loss
// ---------------------------------------------------------------------------
__global__ void k_init(float* __restrict__ out) {
    int i = blockIdx.x * blockDim.x + threadIdx.x;
    const int nz = 2097152 + 8192;
    if (i < nz)  out[OUT_DW + i] = 0.0f;
    if (i == 0)  g_loss = 0.0;
}

// ---------------------------------------------------------------------------
// K0b: per-code |e|^2 and per-token |x|^2 (exact fp32)
// ---------------------------------------------------------------------------
__global__ void k_norms(const float* __restrict__ z, const float* __restrict__ E) {
    int t = blockIdx.x * 256 + threadIdx.x;
    if (t < KCODES) {
        float s = 0.0f;
        #pragma unroll 8
        for (int d = 0; d < DD; d++) { float v = E[d * KCODES + t]; s += v * v; }
        g_e2[t] = s;
    } else if (t < KCODES + NTOK) {
        int n = t - KCODES;
        int b = n / HW, hw = n % HW;
        const float* zp = z + b * DD * HW + hw;
        float s = 0.0f;
        #pragma unroll 8
        for (int d = 0; d < DD; d++) { float v = zp[d * HW]; s += v * v; }
        g_sx2[n] = s;
    }
}

// ---------------------------------------------------------------------------
// K_prep: transpose + bf16 hi/lo split. Blocks 0..255: z -> g_A (32 tok each).
// Blocks 256..511: E -> g_B (32 codes each).
//   A row: [xh | xh | xl]      B row: [eh | el | eh]
// ---------------------------------------------------------------------------
__global__ void k_prep(const float* __restrict__ z, const float* __restrict__ E) {
    __shared__ float st[32 * 264];
    int tid = threadIdx.x;
    bool isB = blockIdx.x >= 256;
    int n0 = (isB ? (blockIdx.x - 256) : blockIdx.x) * 32;

    for (int i = tid; i < 32 * 256; i += 256) {
        int k = i >> 5, nl = i & 31;
        float v;
        if (isB) v = E[k * KCODES + n0 + nl];
        else {
            int b = n0 >> 10, hw0 = n0 & 1023;
            v = z[(b * DD + k) * HW + hw0 + nl];
        }
        st[nl * 264 + k] = v;
    }
    __syncthreads();

    __nv_bfloat16* dst = isB ? g_B : g_A;
    int nl = tid >> 3;
    int jb = (tid & 7) * 32;
    __nv_bfloat16* rowp = dst + (ull)(n0 + nl) * KTOT;
    #pragma unroll 8
    for (int j = 0; j < 32; j++) {
        float v = st[nl * 264 + jb + j];
        __nv_bfloat16 h = __float2bfloat16(v);
        __nv_bfloat16 l = __float2bfloat16(v - __bfloat162float(h));
        rowp[jb + j]       = h;
        rowp[256 + jb + j] = isB ? l : h;
        rowp[512 + jb + j] = isB ? h : l;
    }
}

// ---------------------------------------------------------------------------
// K1: HMMA bf16 distance GEMM fused with per-token top-2.
// Grid (32 token-tiles, 64 code-tiles). 256 threads = 8 warps (4m x 2n),
// warp tile 64x64, 4-stage cp.async pipeline, XOR-swizzled smem, one
// __syncthreads per K stage.
// ---------------------------------------------------------------------------
__global__ void __launch_bounds__(256, 1)
k_mma() {
    extern __shared__ char smem[];
    const uint sb  = smem_u32(smem);
    const uint sA  = sb;                       // 4 x 32KB
    const uint sB  = sb + NPIPE * ABYTES;      // 4 x 16KB

    const int tid  = threadIdx.x;
    const int lane = tid & 31;
    const int wid  = tid >> 5;
    const int wm   = wid & 3;       // m warp (4)
    const int wn   = wid >> 2;      // n warp (2)

    const int m0   = blockIdx.x * MTILE;
    const int nblk = blockIdx.y;
    const int n0   = nblk * NTILE;

    const __nv_bfloat16* gA = g_A + (ull)m0 * KTOT;
    const __nv_bfloat16* gB = g_B + (ull)n0 * KTOT;

    float c[4][8][4];
    #pragma unroll
    for (int i = 0; i < 4; i++)
        #pragma unroll
        for (int j = 0; j < 8; j++)
            #pragma unroll
            for (int r = 0; r < 4; r++) c[i][j][r] = 0.0f;

    // --- hoisted issue-side address components (tid-constant) ---
    const int ld_row = tid >> 3;           // base row within 32-row group
    const int ld_ch  = tid & 7;            // 16B chunk (0..7), constant
    const uint ld_sw = (uint)((ld_ch ^ (ld_row & 7)) << 4);   // swizzle, constant
    const uint dst_base = (uint)ld_row * 128u + ld_sw;
    const __nv_bfloat16* srcA0 = gA + (ull)ld_row * KTOT + ld_ch * 8;
    const __nv_bfloat16* srcB0 = gB + (ull)ld_row * KTOT + ld_ch * 8;

    // --- hoisted ldmatrix address components ---
    const int rowA = wm * 64 + (lane & 7) + ((lane >> 3) & 1) * 8;  // + i*16
    const int chA  = (lane >> 4);
    const int rowB = wn * 64 + (lane & 7) + ((lane >> 4) << 3);     // + nb*16
    const int chB  = (lane >> 3) & 1;
    uint colA[4], colB[4];
    #pragma unroll
    for (int ks = 0; ks < 4; ks++) {
        colA[ks] = (uint)(((ks * 2 + chA) ^ (rowA & 7)) << 4);
        colB[ks] = (uint)(((ks * 2 + chB) ^ (rowB & 7)) << 4);
    }
    uint rbaseA[4], rbaseB[4];
    #pragma unroll
    for (int i = 0; i < 4; i++) rbaseA[i] = (uint)(rowA + i * 16) * 128u;
    #pragma unroll
    for (int i = 0; i < 4; i++) rbaseB[i] = (uint)(rowB + i * 16) * 128u;

    // stage issuer: 8 A-chunks + 4 B-chunks of 16B per thread
    auto issue = [&](int s) {
        const int kb = s * KS;
        const uint bufA = sA + (uint)(s & (NPIPE - 1)) * ABYTES;
        const uint bufB = sB + (uint)(s & (NPIPE - 1)) * BBYTES;
        const __nv_bfloat16* sa = srcA0 + kb;
        const __nv_bfloat16* sbp = srcB0 + kb;
        #pragma unroll
        for (int i = 0; i < 8; i++)
            CP16(bufA + dst_base + (uint)i * 4096u, sa + (ull)i * 32 * KTOT);
        #pragma unroll
        for (int i = 0; i < 4; i++)
            CP16(bufB + dst_base + (uint)i * 4096u, sbp + (ull)i * 32 * KTOT);
        CP_COMMIT();
    };

    issue(0); issue(1); issue(2);

    for (int s = 0; s < NSTAGES; s++) {
        if (s < NSTAGES - 2)       { CP_WAIT(2); }
        else if (s == NSTAGES - 2) { CP_WAIT(1); }
        else                       { CP_WAIT(0); }
        __syncthreads();

        const uint bufA = sA + (uint)(s & (NPIPE - 1)) * ABYTES;
        const uint bufB = sB + (uint)(s & (NPIPE - 1)) * BBYTES;

        #pragma unroll
        for (int ks = 0; ks < 4; ks++) {
            uint a[4][4];
            #pragma unroll
            for (int i = 0; i < 4; i++)
                LDSM4(a[i][0], a[i][1], a[i][2], a[i][3],
                      bufA + rbaseA[i] + colA[ks]);
            uint b[8][2];
            #pragma unroll
            for (int nb = 0; nb < 4; nb++) {
                uint r0, r1, r2, r3;
                LDSM4(r0, r1, r2, r3, bufB + rbaseB[nb] + colB[ks]);
                b[nb * 2][0] = r0;     b[nb * 2][1] = r1;
                b[nb * 2 + 1][0] = r2; b[nb * 2 + 1][1] = r3;
            }
            #pragma unroll
            for (int i = 0; i < 4; i++)
                #pragma unroll
                for (int j = 0; j < 8; j++)
                    MMA16816(c[i][j], a[i], b[j]);
        }
        if (s + 3 < NSTAGES) issue(s + 3);
    }

    // ---------------- epilogue: dist + top-2, no atomics --------------------
    __syncthreads();                // all warps done with smem tiles
    ull* sred = (ull*)smem;         // [256 rows][2 warp_n][2]

    float e2v[8][2];
    #pragma unroll
    for (int j = 0; j < 8; j++)
        #pragma unroll
        for (int q = 0; q < 2; q++)
            e2v[j][q] = g_e2[n0 + wn * 64 + j * 8 + (lane & 3) * 2 + q];

    #pragma unroll
    for (int i = 0; i < 4; i++) {
        #pragma unroll
        for (int h = 0; h < 2; h++) {
            const int m_local = wm * 64 + i * 16 + (lane >> 2) + h * 8;
            const float sx2 = g_sx2[m0 + m_local];
            ull b1 = 0ull, b2 = 0ull;
            #pragma unroll
            for (int j = 0; j < 8; j++) {
                #pragma unroll
                for (int q = 0; q < 2; q++) {
                    float dot  = c[i][j][h * 2 + q];
                    float dist = (sx2 - 2.0f * dot) + e2v[j][q];
                    const int n = n0 + wn * 64 + j * 8 + (lane & 3) * 2 + q;
                    uint u = __float_as_uint(dist);
                    uint m = (u & 0x80000000u) ? ~u : (u | 0x80000000u);
                    ull key = ((ull)(~m) << 32) | (uint)(KCODES - 1 - n);
                    if (key > b1)      { b2 = b1; b1 = key; }
                    else if (key > b2) { b2 = key; }
                }
            }
            #pragma unroll
            for (int sh = 1; sh <= 2; sh <<= 1) {
                ull o1 = __shfl_xor_sync(0xffffffffu, b1, sh);
                ull o2 = __shfl_xor_sync(0xffffffffu, b2, sh);
                ull n1 = umax(b1, o1);
                ull n2 = umax(umin(b1, o1), umax(b2, o2));
                b1 = n1; b2 = n2;
            }
            if ((lane & 3) == 0) {
                sred[(m_local * 2 + wn) * 2 + 0] = b1;
                sred[(m_local * 2 + wn) * 2 + 1] = b2;
            }
        }
    }
    __syncthreads();
    {
        const int row = tid;
        ull p1a = sred[(row * 2 + 0) * 2 + 0], p2a = sred[(row * 2 + 0) * 2 + 1];
        ull p1b = sred[(row * 2 + 1) * 2 + 0], p2b = sred[(row * 2 + 1) * 2 + 1];
        ull b1 = umax(p1a, p1b);
        ull b2 = umax(umin(p1a, p1b), umax(p2a, p2b));
        g_top1[nblk * NTOK + m0 + row] = b1;
        g_top2[nblk * NTOK + m0 + row] = b2;
    }
}

// ---------------------------------------------------------------------------
// K2a: merge per-split top-2, near-tie exact fp32 fixup, emit idx + cs
// ---------------------------------------------------------------------------
__device__ __forceinline__ float exact_dist(const float* z, const float* E,
                                            int n, int k) {
    int b = n >> 10, hw = n & 1023;
    const float* zp = z + b * DD * HW + hw;
    const float* ep = E + k;
    float dot = 0.0f;
    #pragma unroll 8
    for (int d = 0; d < DD; d++) dot = fmaf(zp[d * HW], ep[d * KCODES], dot);
    return (g_sx2[n] - 2.0f * dot) + g_e2[k];
}

__global__ void k_assign(const float* __restrict__ z, const float* __restrict__ E,
                         float* __restrict__ out) {
    int n = blockIdx.x * 256 + threadIdx.x;
    if (n >= NTOK) return;
    ull b1 = 0ull, b2 = 0ull;
    for (int s = 0; s < NSPLITS; s++) {
        ull t1 = g_top1[s * NTOK + n];
        ull t2 = g_top2[s * NTOK + n];
        if (t1 > b1)      { b2 = b1; b1 = t1; }
        else if (t1 > b2) { b2 = t1; }
        if (t2 > b2)      { b2 = t2; }
    }
    int i1 = (KCODES - 1) - (int)(uint)(b1 & 0xffffffffu);
    int i2 = (KCODES - 1) - (int)(uint)(b2 & 0xffffffffu);
    uint m1 = ~(uint)(b1 >> 32), m2 = ~(uint)(b2 >> 32);
    float d1 = __uint_as_float((m1 & 0x80000000u) ? (m1 & 0x7fffffffu) : ~m1);
    float d2 = __uint_as_float((m2 & 0x80000000u) ? (m2 & 0x7fffffffu) : ~m2);
    int idx = i1;
    if (d2 - d1 < 2e-4f) {   // near-tie: exact fp32 re-score (reference math)
        float e1  = exact_dist(z, E, n, i1);
        float e2x = exact_dist(z, E, n, i2);
        if (e2x < e1 || (e2x == e1 && i2 < i1)) idx = i2;
    }
    g_idx[n] = idx;
    out[OUT_IDX + n] = (float)idx;
    atomicAdd(&out[OUT_CS + idx], 1.0f);
}

// ---------------------------------------------------------------------------
// K2b: gather quantized (NCHW), scatter dw, accumulate loss
// ---------------------------------------------------------------------------
__global__ void k_scatter(const float* __restrict__ z, const float* __restrict__ E,
                          float* __restrict__ out) {
    int tx = threadIdx.x & 31;
    int ty = threadIdx.x >> 5;
    int hw = blockIdx.x * 32 + tx;
    int d  = blockIdx.y * 8 + ty;
    int b  = blockIdx.z;

    int n   = b * HW + hw;
    int idx = g_idx[n];
    float q  = E[d * KCODES + idx];
    int   zi = (b * DD + d) * HW + hw;
    float zv = z[zi];
    out[OUT_Q + zi] = q;
    float diff = q - zv;
    atomicAdd(&out[OUT_DW + d * KCODES + idx], zv);

    __shared__ float red[256];
    red[threadIdx.x] = diff * diff;
    __syncthreads();
    #pragma unroll
    for (int s = 128; s > 0; s >>= 1) {
        if (threadIdx.x < s) red[threadIdx.x] += red[threadIdx.x + s];
        __syncthreads();
    }
    if (threadIdx.x == 0) atomicAdd(&g_loss, (double)red[0]);
}

// ---------------------------------------------------------------------------
// K3: loss + perplexity
// ---------------------------------------------------------------------------
__global__ void k_final(float* __restrict__ out) {
    __shared__ float red[256];
    int t = threadIdx.x;
    float s = 0.0f;
    for (int k = t; k < KCODES; k += 256) {
        float p = out[OUT_CS + k] * (1.0f / 8192.0f);
        s += p * logf(p + 1e-10f);
    }
    red[t] = s;
    __syncthreads();
    #pragma unroll
    for (int st = 128; st > 0; st >>= 1) {
        if (t < st) red[t] += red[t + st];
        __syncthreads();
    }
    if (t == 0) {
        out[OUT_PERP] = expf(-red[0]);
        out[OUT_LOSS] = (float)(0.25 * g_loss / 2097152.0);
    }
}

// ---------------------------------------------------------------------------
extern "C" void kernel_launch(void* const* d_in, const int* in_sizes, int n_in,
                              void* d_out, int out_size) {
    const float* z = (const float*)d_in[0];         // [8,256,32,32]
    const float* E = (const float*)d_in[1];         // [256,8192]
    float* out = (float*)d_out;

    cudaFuncSetAttribute(k_mma, cudaFuncAttributeMaxDynamicSharedMemorySize,
                         SMEM_DYN);

    k_init   <<< (2097152 + 8192 + 255) / 256, 256 >>>(out);
    k_norms  <<< (KCODES + NTOK + 255) / 256, 256 >>>(z, E);
    k_prep   <<< 512, 256 >>>(z, E);
    k_mma    <<< dim3(NTOK / MTILE, NSPLITS), 256, SMEM_DYN >>>();
    k_assign <<< NTOK / 256, 256 >>>(z, E, out);
    k_scatter<<< dim3(HW / 32, DD / 8, BATCH), 256 >>>(z, E, out);
    k_final  <<< 1, 256 >>>(out);
}

// round 6
// speedup vs baseline: 2.8585x; 1.0350x over previous
#include <cuda_runtime.h>
#include <cuda_bf16.h>
#include <math.h>

// Problem constants
#define DD      256
#define KCODES  8192
#define BATCH   8
#define HW      1024
#define NTOK    8192

// Output layout (flattened return tuple, in order)
#define OUT_Q     0
#define OUT_LOSS  2097152
#define OUT_PERP  2097153
#define OUT_IDX   2097154
#define OUT_DW    2105346
#define OUT_CS    4202498

// GEMM config: C[8192 tok, 8192 codes] = A[.,768] * B[.,768]^T  (bf16x3 split)
#define KTOT    768
#define MTILE   256
#define NTILE   128
#define KS      64
#define NSTAGES 12                    // 768/64
#define NPIPE   4                     // cp.async pipeline depth
#define NSPLITS (KCODES / NTILE)      // 64
#define ABYTES  32768                 // per-stage A buffer
#define BBYTES  16384                 // per-stage B buffer
#define SMEM_DYN (NPIPE * (ABYTES + BBYTES))   // 192KB

typedef unsigned long long ull;
typedef unsigned int uint;

// ---------------- device scratch (no allocation allowed) --------------------
__device__ __nv_bfloat16 g_A[NTOK   * KTOT];  // [tok ][xh(256)|xh(256)|xl(256)]
__device__ __nv_bfloat16 g_B[KCODES * KTOT];  // [code][eh(256)|el(256)|eh(256)]
__device__ float  g_e2[KCODES];
__device__ float  g_sx2[NTOK];
__device__ ull    g_top1[NTOK * NSPLITS];     // [token][split]  (coalesced merge)
__device__ ull    g_top2[NTOK * NSPLITS];
__device__ int    g_idx[NTOK];
__device__ double g_loss;

// ---------------- PTX helpers (all plain-sm_100 legal) ----------------------
__device__ __forceinline__ uint smem_u32(const void* p) {
    uint a;
    asm("{ .reg .u64 t; cvta.to.shared.u64 t, %1; cvt.u32.u64 %0, t; }"
        : "=r"(a) : "l"(p));
    return a;
}
#define CP16(dst, src) \
    asm volatile("cp.async.cg.shared.global [%0], [%1], 16;" :: "r"(dst), "l"(src))
#define CP_COMMIT() asm volatile("cp.async.commit_group;")
#define CP_WAIT(n)  asm volatile("cp.async.wait_group %0;" :: "n"(n))

#define LDSM4(r0, r1, r2, r3, a) \
    asm volatile("ldmatrix.sync.aligned.m8n8.x4.shared.b16 {%0,%1,%2,%3}, [%4];" \
        : "=r"(r0), "=r"(r1), "=r"(r2), "=r"(r3) : "r"(a))

#define MMA16816(c, a, b) \
    asm volatile("mma.sync.aligned.m16n8k16.row.col.f32.bf16.bf16.f32 " \
        "{%0,%1,%2,%3}, {%4,%5,%6,%7}, {%8,%9}, {%0,%1,%2,%3};" \
        : "+f"((c)[0]), "+f"((c)[1]), "+f"((c)[2]), "+f"((c)[3]) \
        : "r"((a)[0]), "r"((a)[1]), "r"((a)[2]), "r"((a)[3]), \
          "r"((b)[0]), "r"((b)[1]))

__device__ __forceinline__ ull umax(ull a, ull b) { return a > b ? a : b; }
__device__ __forceinline__ ull umin(ull a, ull b) { return a < b ? a : b; }

// ---------------------------------------------------------------------------
// K0: zero dw + cluster_size region, g_loss
// ---------------------------------------------------------------------------
__global__ void k_init(float* __restrict__ out) {
    int i = blockIdx.x * blockDim.x + threadIdx.x;
    const int nz = 2097152 + 8192;
    if (i < nz)  out[OUT_DW + i] = 0.0f;
    if (i == 0)  g_loss = 0.0;
}

// ---------------------------------------------------------------------------
// K0b: per-code |e|^2 and per-token |x|^2 (exact fp32)
// ---------------------------------------------------------------------------
__global__ void k_norms(const float* __restrict__ z, const float* __restrict__ E) {
    int t = blockIdx.x * 256 + threadIdx.x;
    if (t < KCODES) {
        float s = 0.0f;
        #pragma unroll 8
        for (int d = 0; d < DD; d++) { float v = E[d * KCODES + t]; s += v * v; }
        g_e2[t] = s;
    } else if (t < KCODES + NTOK) {
        int n = t - KCODES;
        int b = n / HW, hw = n % HW;
        const float* zp = z + b * DD * HW + hw;
        float s = 0.0f;
        #pragma unroll 8
        for (int d = 0; d < DD; d++) { float v = zp[d * HW]; s += v * v; }
        g_sx2[n] = s;
    }
}

// ---------------------------------------------------------------------------
// K_prep: transpose + bf16 hi/lo split. Blocks 0..255: z -> g_A (32 tok each).
// Blocks 256..511: E -> g_B (32 codes each).
//   A row: [xh | xh | xl]      B row: [eh | el | eh]
// ---------------------------------------------------------------------------
__global__ void k_prep(const float* __restrict__ z, const float* __restrict__ E) {
    __shared__ float st[32 * 264];
    int tid = threadIdx.x;
    bool isB = blockIdx.x >= 256;
    int n0 = (isB ? (blockIdx.x - 256) : blockIdx.x) * 32;

    for (int i = tid; i < 32 * 256; i += 256) {
        int k = i >> 5, nl = i & 31;
        float v;
        if (isB) v = E[k * KCODES + n0 + nl];
        else {
            int b = n0 >> 10, hw0 = n0 & 1023;
            v = z[(b * DD + k) * HW + hw0 + nl];
        }
        st[nl * 264 + k] = v;
    }
    __syncthreads();

    __nv_bfloat16* dst = isB ? g_B : g_A;
    int nl = tid >> 3;
    int jb = (tid & 7) * 32;
    __nv_bfloat16* rowp = dst + (ull)(n0 + nl) * KTOT;
    #pragma unroll 8
    for (int j = 0; j < 32; j++) {
        float v = st[nl * 264 + jb + j];
        __nv_bfloat16 h = __float2bfloat16(v);
        __nv_bfloat16 l = __float2bfloat16(v - __bfloat162float(h));
        rowp[jb + j]       = h;
        rowp[256 + jb + j] = isB ? l : h;
        rowp[512 + jb + j] = isB ? h : l;
    }
}

// ---------------------------------------------------------------------------
// K1: HMMA bf16 distance GEMM fused with per-token top-2.
// Grid (32 token-tiles, 64 code-tiles). 512 threads = 16 warps (4m x 4n),
// warp tile 64x32 (64 fp32 acc regs -> fits 512 thr in 64K regs, 4 warps/SMSP),
// 4-stage cp.async pipeline, XOR-swizzled smem, one __syncthreads per stage.
// ---------------------------------------------------------------------------
__global__ void __launch_bounds__(512, 1)
k_mma() {
    extern __shared__ char smem[];
    const uint sb  = smem_u32(smem);
    const uint sA  = sb;                       // 4 x 32KB
    const uint sB  = sb + NPIPE * ABYTES;      // 4 x 16KB

    const int tid  = threadIdx.x;
    const int lane = tid & 31;
    const int wid  = tid >> 5;
    const int wm   = wid & 3;       // m warp (4): 64 rows each
    const int wn   = wid >> 2;      // n warp (4): 32 cols each

    const int m0   = blockIdx.x * MTILE;
    const int nblk = blockIdx.y;
    const int n0   = nblk * NTILE;

    const __nv_bfloat16* gA = g_A + (ull)m0 * KTOT;
    const __nv_bfloat16* gB = g_B + (ull)n0 * KTOT;

    float c[4][4][4];
    #pragma unroll
    for (int i = 0; i < 4; i++)
        #pragma unroll
        for (int j = 0; j < 4; j++)
            #pragma unroll
            for (int r = 0; r < 4; r++) c[i][j][r] = 0.0f;

    // --- hoisted issue-side address components (tid-constant) ---
    const int ld_row = tid >> 3;           // 0..63
    const int ld_ch  = tid & 7;            // 16B chunk
    const uint ld_sw = (uint)((ld_ch ^ (ld_row & 7)) << 4);
    const uint dst_base = (uint)ld_row * 128u + ld_sw;
    const __nv_bfloat16* srcA0 = gA + (ull)ld_row * KTOT + ld_ch * 8;
    const __nv_bfloat16* srcB0 = gB + (ull)ld_row * KTOT + ld_ch * 8;

    // --- hoisted ldmatrix address components ---
    const int rowA = wm * 64 + (lane & 7) + ((lane >> 3) & 1) * 8;  // + i*16
    const int chA  = (lane >> 4);
    const int rowB = wn * 32 + (lane & 7) + ((lane >> 4) << 3);     // + nb*16
    const int chB  = (lane >> 3) & 1;
    uint colA[4], colB[4];
    #pragma unroll
    for (int ks = 0; ks < 4; ks++) {
        colA[ks] = (uint)(((ks * 2 + chA) ^ (rowA & 7)) << 4);
        colB[ks] = (uint)(((ks * 2 + chB) ^ (rowB & 7)) << 4);
    }
    uint rbaseA[4], rbaseB[2];
    #pragma unroll
    for (int i = 0; i < 4; i++) rbaseA[i] = (uint)(rowA + i * 16) * 128u;
    #pragma unroll
    for (int i = 0; i < 2; i++) rbaseB[i] = (uint)(rowB + i * 16) * 128u;

    // stage issuer: 4 A-chunks + 2 B-chunks of 16B per thread (512 threads)
    auto issue = [&](int s) {
        const int kb = s * KS;
        const uint bufA = sA + (uint)(s & (NPIPE - 1)) * ABYTES;
        const uint bufB = sB + (uint)(s & (NPIPE - 1)) * BBYTES;
        const __nv_bfloat16* sa  = srcA0 + kb;
        const __nv_bfloat16* sbp = srcB0 + kb;
        #pragma unroll
        for (int i = 0; i < 4; i++)
            CP16(bufA + dst_base + (uint)i * 8192u, sa + (ull)i * 64 * KTOT);
        #pragma unroll
        for (int i = 0; i < 2; i++)
            CP16(bufB + dst_base + (uint)i * 8192u, sbp + (ull)i * 64 * KTOT);
        CP_COMMIT();
    };

    issue(0); issue(1); issue(2);

    for (int s = 0; s < NSTAGES; s++) {
        if (s < NSTAGES - 2)       { CP_WAIT(2); }
        else if (s == NSTAGES - 2) { CP_WAIT(1); }
        else                       { CP_WAIT(0); }
        __syncthreads();

        const uint bufA = sA + (uint)(s & (NPIPE - 1)) * ABYTES;
        const uint bufB = sB + (uint)(s & (NPIPE - 1)) * BBYTES;

        #pragma unroll
        for (int ks = 0; ks < 4; ks++) {
            uint a[4][4];
            #pragma unroll
            for (int i = 0; i < 4; i++)
                LDSM4(a[i][0], a[i][1], a[i][2], a[i][3],
                      bufA + rbaseA[i] + colA[ks]);
            uint b[4][2];
            #pragma unroll
            for (int nb = 0; nb < 2; nb++) {
                uint r0, r1, r2, r3;
                LDSM4(r0, r1, r2, r3, bufB + rbaseB[nb] + colB[ks]);
                b[nb * 2][0] = r0;     b[nb * 2][1] = r1;
                b[nb * 2 + 1][0] = r2; b[nb * 2 + 1][1] = r3;
            }
            #pragma unroll
            for (int i = 0; i < 4; i++)
                #pragma unroll
                for (int j = 0; j < 4; j++)
                    MMA16816(c[i][j], a[i], b[j]);
        }
        if (s + 3 < NSTAGES) issue(s + 3);
    }

    // ---------------- epilogue: dist + top-2, no atomics --------------------
    __syncthreads();                // all warps done with smem tiles
    ull* sred = (ull*)smem;         // [256 rows][4 warp_n][2] = 16KB

    float e2v[4][2];
    #pragma unroll
    for (int j = 0; j < 4; j++)
        #pragma unroll
        for (int q = 0; q < 2; q++)
            e2v[j][q] = g_e2[n0 + wn * 32 + j * 8 + (lane & 3) * 2 + q];

    #pragma unroll
    for (int i = 0; i < 4; i++) {
        #pragma unroll
        for (int h = 0; h < 2; h++) {
            const int m_local = wm * 64 + i * 16 + (lane >> 2) + h * 8;
            const float sx2 = g_sx2[m0 + m_local];
            ull b1 = 0ull, b2 = 0ull;
            #pragma unroll
            for (int j = 0; j < 4; j++) {
                #pragma unroll
                for (int q = 0; q < 2; q++) {
                    float dot  = c[i][j][h * 2 + q];
                    float dist = (sx2 - 2.0f * dot) + e2v[j][q];
                    const int n = n0 + wn * 32 + j * 8 + (lane & 3) * 2 + q;
                    uint u = __float_as_uint(dist);
                    uint m = (u & 0x80000000u) ? ~u : (u | 0x80000000u);
                    ull key = ((ull)(~m) << 32) | (uint)(KCODES - 1 - n);
                    if (key > b1)      { b2 = b1; b1 = key; }
                    else if (key > b2) { b2 = key; }
                }
            }
            #pragma unroll
            for (int sh = 1; sh <= 2; sh <<= 1) {
                ull o1 = __shfl_xor_sync(0xffffffffu, b1, sh);
                ull o2 = __shfl_xor_sync(0xffffffffu, b2, sh);
                ull n1 = umax(b1, o1);
                ull n2 = umax(umin(b1, o1), umax(b2, o2));
                b1 = n1; b2 = n2;
            }
            if ((lane & 3) == 0) {
                sred[(m_local * 4 + wn) * 2 + 0] = b1;
                sred[(m_local * 4 + wn) * 2 + 1] = b2;
            }
        }
    }
    __syncthreads();
    if (tid < 256) {
        const int row = tid;
        ull b1 = 0ull, b2 = 0ull;
        #pragma unroll
        for (int w = 0; w < 4; w++) {
            ull t1 = sred[(row * 4 + w) * 2 + 0];
            ull t2 = sred[(row * 4 + w) * 2 + 1];
            if (t1 > b1)      { b2 = b1; b1 = t1; }
            else if (t1 > b2) { b2 = t1; }
            if (t2 > b2)      { b2 = t2; }
        }
        g_top1[(ull)(m0 + row) * NSPLITS + nblk] = b1;
        g_top2[(ull)(m0 + row) * NSPLITS + nblk] = b2;
    }
}

// ---------------------------------------------------------------------------
// K2a: warp-per-token split merge + near-tie exact fp32 fixup (lane-parallel)
// ---------------------------------------------------------------------------
__global__ void k_assign(const float* __restrict__ z, const float* __restrict__ E,
                         float* __restrict__ out) {
    const int gtid = blockIdx.x * 256 + threadIdx.x;
    const int n    = gtid >> 5;          // token = warp
    const int lane = gtid & 31;
    if (n >= NTOK) return;

    // merge 64 splits (2 per lane), coalesced: [token][split]
    const ull* t1p = g_top1 + (ull)n * NSPLITS;
    const ull* t2p = g_top2 + (ull)n * NSPLITS;
    ull b1 = 0ull, b2 = 0ull;
    #pragma unroll
    for (int r = 0; r < 2; r++) {
        int s = lane + r * 32;
        ull t1 = t1p[s], t2 = t2p[s];
        if (t1 > b1)      { b2 = b1; b1 = t1; }
        else if (t1 > b2) { b2 = t1; }
        if (t2 > b2)      { b2 = t2; }
    }
    #pragma unroll
    for (int sh = 16; sh >= 1; sh >>= 1) {
        ull o1 = __shfl_xor_sync(0xffffffffu, b1, sh);
        ull o2 = __shfl_xor_sync(0xffffffffu, b2, sh);
        ull n1 = umax(b1, o1);
        ull n2 = umax(umin(b1, o1), umax(b2, o2));
        b1 = n1; b2 = n2;
    }

    int i1 = (KCODES - 1) - (int)(uint)(b1 & 0xffffffffu);
    int i2 = (KCODES - 1) - (int)(uint)(b2 & 0xffffffffu);
    uint m1 = ~(uint)(b1 >> 32), m2 = ~(uint)(b2 >> 32);
    float d1 = __uint_as_float((m1 & 0x80000000u) ? (m1 & 0x7fffffffu) : ~m1);
    float d2 = __uint_as_float((m2 & 0x80000000u) ? (m2 & 0x7fffffffu) : ~m2);

    int idx = i1;
    if (d2 - d1 < 2e-4f) {
        // exact fp32 re-score, lane-parallel (8 dims/lane), same bucketed form
        int b = n >> 10, hw = n & 1023;
        const float* zp  = z + b * DD * HW + hw;
        const float* ep1 = E + i1;
        const float* ep2 = E + i2;
        float dot1 = 0.0f, dot2 = 0.0f;
        #pragma unroll
        for (int t = 0; t < 8; t++) {
            int d = t * 32 + lane;
            float zv = zp[d * HW];
            dot1 = fmaf(zv, ep1[d * KCODES], dot1);
            dot2 = fmaf(zv, ep2[d * KCODES], dot2);
        }
        #pragma unroll
        for (int sh = 16; sh >= 1; sh >>= 1) {
            dot1 += __shfl_xor_sync(0xffffffffu, dot1, sh);
            dot2 += __shfl_xor_sync(0xffffffffu, dot2, sh);
        }
        float sx2 = g_sx2[n];
        float e1  = (sx2 - 2.0f * dot1) + g_e2[i1];
        float e2x = (sx2 - 2.0f * dot2) + g_e2[i2];
        if (e2x < e1 || (e2x == e1 && i2 < i1)) idx = i2;
    }
    if (lane == 0) {
        g_idx[n] = idx;
        out[OUT_IDX + n] = (float)idx;
        atomicAdd(&out[OUT_CS + idx], 1.0f);
    }
}

// ---------------------------------------------------------------------------
// K2b: gather quantized (NCHW), scatter dw, accumulate loss
// ---------------------------------------------------------------------------
__global__ void k_scatter(const float* __restrict__ z, const float* __restrict__ E,
                          float* __restrict__ out) {
    int tx = threadIdx.x & 31;
    int ty = threadIdx.x >> 5;
    int hw = blockIdx.x * 32 + tx;
    int d  = blockIdx.y * 8 + ty;
    int b  = blockIdx.z;

    int n   = b * HW + hw;
    int idx = g_idx[n];
    float q  = E[d * KCODES + idx];
    int   zi = (b * DD + d) * HW + hw;
    float zv = z[zi];
    out[OUT_Q + zi] = q;
    float diff = q - zv;
    atomicAdd(&out[OUT_DW + d * KCODES + idx], zv);

    __shared__ float red[256];
    red[threadIdx.x] = diff * diff;
    __syncthreads();
    #pragma unroll
    for (int s = 128; s > 0; s >>= 1) {
        if (threadIdx.x < s) red[threadIdx.x] += red[threadIdx.x + s];
        __syncthreads();
    }
    if (threadIdx.x == 0) atomicAdd(&g_loss, (double)red[0]);
}

// ---------------------------------------------------------------------------
// K3: loss + perplexity
// ---------------------------------------------------------------------------
__global__ void k_final(float* __restrict__ out) {
    __shared__ float red[256];
    int t = threadIdx.x;
    float s = 0.0f;
    for (int k = t; k < KCODES; k += 256) {
        float p = out[OUT_CS + k] * (1.0f / 8192.0f);
        s += p * logf(p + 1e-10f);
    }
    red[t] = s;
    __syncthreads();
    #pragma unroll
    for (int st = 128; st > 0; st >>= 1) {
        if (t < st) red[t] += red[t + st];
        __syncthreads();
    }
    if (t == 0) {
        out[OUT_PERP] = expf(-red[0]);
        out[OUT_LOSS] = (float)(0.25 * g_loss / 2097152.0);
    }
}

// ---------------------------------------------------------------------------
extern "C" void kernel_launch(void* const* d_in, const int* in_sizes, int n_in,
                              void* d_out, int out_size) {
    const float* z = (const float*)d_in[0];         // [8,256,32,32]
    const float* E = (const float*)d_in[1];         // [256,8192]
    float* out = (float*)d_out;

    cudaFuncSetAttribute(k_mma, cudaFuncAttributeMaxDynamicSharedMemorySize,
                         SMEM_DYN);

    k_init   <<< (2097152 + 8192 + 255) / 256, 256 >>>(out);
    k_norms  <<< (KCODES + NTOK + 255) / 256, 256 >>>(z, E);
    k_prep   <<< 512, 256 >>>(z, E);
    k_mma    <<< dim3(NTOK / MTILE, NSPLITS), 512, SMEM_DYN >>>();
    k_assign <<< (NTOK * 32) / 256, 256 >>>(z, E, out);
    k_scatter<<< dim3(HW / 32, DD / 8, BATCH), 256 >>>(z, E, out);
    k_final  <<< 1, 256 >>>(out);
}

// round 7
// speedup vs baseline: 3.0088x; 1.0526x over previous
#include <cuda_runtime.h>
#include <cuda_bf16.h>
#include <math.h>

// Problem constants
#define DD      256
#define KCODES  8192
#define BATCH   8
#define HW      1024
#define NTOK    8192

// Output layout (flattened return tuple, in order)
#define OUT_Q     0
#define OUT_LOSS  2097152
#define OUT_PERP  2097153
#define OUT_IDX   2097154
#define OUT_DW    2105346
#define OUT_CS    4202498

// GEMM config: C[8192 tok, 8192 codes] = A[.,768] * B[.,768]^T  (bf16x3 split)
#define KTOT    768
#define MTILE   256
#define NTILE   128
#define KS      64
#define NSTAGES 12                    // 768/64
#define NPIPE   4                     // cp.async pipeline depth
#define NSPLITS (KCODES / NTILE)      // 64
#define ABYTES  32768                 // per-stage A buffer
#define BBYTES  16384                 // per-stage B buffer
#define SMEM_DYN (NPIPE * (ABYTES + BBYTES))   // 192KB

typedef unsigned long long ull;
typedef unsigned int uint;

// ---------------- device scratch (no allocation allowed) --------------------
__device__ __nv_bfloat16 g_A[NTOK   * KTOT];  // [tok ][xh(256)|xh(256)|xl(256)]
__device__ __nv_bfloat16 g_B[KCODES * KTOT];  // [code][eh(256)|el(256)|eh(256)]
__device__ float  g_e2[KCODES];
__device__ float  g_sx2[NTOK];
__device__ ull    g_top1[NTOK * NSPLITS];     // [token][split]  (coalesced merge)
__device__ ull    g_top2[NTOK * NSPLITS];
__device__ int    g_idx[NTOK];
__device__ double g_loss;

// ---------------- PTX helpers (all plain-sm_100 legal) ----------------------
__device__ __forceinline__ uint smem_u32(const void* p) {
    uint a;
    asm("{ .reg .u64 t; cvta.to.shared.u64 t, %1; cvt.u32.u64 %0, t; }"
        : "=r"(a) : "l"(p));
    return a;
}
#define CP16(dst, src) \
    asm volatile("cp.async.cg.shared.global [%0], [%1], 16;" :: "r"(dst), "l"(src))
#define CP_COMMIT() asm volatile("cp.async.commit_group;")
#define CP_WAIT(n)  asm volatile("cp.async.wait_group %0;" :: "n"(n))

#define LDSM4(r0, r1, r2, r3, a) \
    asm volatile("ldmatrix.sync.aligned.m8n8.x4.shared.b16 {%0,%1,%2,%3}, [%4];" \
        : "=r"(r0), "=r"(r1), "=r"(r2), "=r"(r3) : "r"(a))

#define MMA16816(c, a, b) \
    asm volatile("mma.sync.aligned.m16n8k16.row.col.f32.bf16.bf16.f32 " \
        "{%0,%1,%2,%3}, {%4,%5,%6,%7}, {%8,%9}, {%0,%1,%2,%3};" \
        : "+f"((c)[0]), "+f"((c)[1]), "+f"((c)[2]), "+f"((c)[3]) \
        : "r"((a)[0]), "r"((a)[1]), "r"((a)[2]), "r"((a)[3]), \
          "r"((b)[0]), "r"((b)[1]))

__device__ __forceinline__ ull umax(ull a, ull b) { return a > b ? a : b; }
__device__ __forceinline__ ull umin(ull a, ull b) { return a < b ? a : b; }

// ---------------------------------------------------------------------------
// K_prep (fused init + norms + transpose/split):
//   Blocks 0..255:   z -> g_A (32 tokens each) + g_sx2
//   Blocks 256..511: E -> g_B (32 codes each)  + g_e2
//   All blocks cooperatively zero the dw+cs output region; block 0 zeros loss.
//   Norms are computed sequentially over d (identical order/rounding to the
//   k_norms kernel used in all passing rounds -> bit-identical e2/sx2).
// ---------------------------------------------------------------------------
__global__ void k_prep(const float* __restrict__ z, const float* __restrict__ E,
                       float* __restrict__ out) {
    __shared__ float st[32 * 264];
    const int tid = threadIdx.x;
    const bool isB = blockIdx.x >= 256;
    const int n0 = (isB ? (blockIdx.x - 256) : blockIdx.x) * 32;

    // zero dw + cluster_size (2105344 floats = 1052672 float2, 8B-aligned)
    {
        const float2 z2 = make_float2(0.0f, 0.0f);
        float2* dst2 = (float2*)(out + OUT_DW);
        for (int i = blockIdx.x * 256 + tid; i < 1052672; i += 512 * 256)
            dst2[i] = z2;
        if (blockIdx.x == 0 && tid == 0) g_loss = 0.0;
    }

    // load 32 rows x 256 dims into smem (transposed)
    for (int i = tid; i < 32 * 256; i += 256) {
        int k = i >> 5, nl = i & 31;
        float v;
        if (isB) v = E[k * KCODES + n0 + nl];
        else {
            int b = n0 >> 10, hw0 = n0 & 1023;
            v = z[(b * DD + k) * HW + hw0 + nl];
        }
        st[nl * 264 + k] = v;
    }
    __syncthreads();

    // norms: one thread per row, sequential fp32 over d (matches prior rounds)
    if (tid < 32) {
        float s = 0.0f;
        #pragma unroll 8
        for (int d = 0; d < DD; d++) { float v = st[tid * 264 + d]; s += v * v; }
        if (isB) g_e2[n0 + tid] = s;
        else     g_sx2[n0 + tid] = s;
    }

    // bf16 hi/lo split:  A row [xh|xh|xl],  B row [eh|el|eh]
    __nv_bfloat16* dst = isB ? g_B : g_A;
    int nl = tid >> 3;
    int jb = (tid & 7) * 32;
    __nv_bfloat16* rowp = dst + (ull)(n0 + nl) * KTOT;
    #pragma unroll 8
    for (int j = 0; j < 32; j++) {
        float v = st[nl * 264 + jb + j];
        __nv_bfloat16 h = __float2bfloat16(v);
        __nv_bfloat16 l = __float2bfloat16(v - __bfloat162float(h));
        rowp[jb + j]       = h;
        rowp[256 + jb + j] = isB ? l : h;
        rowp[512 + jb + j] = isB ? h : l;
    }
}

// ---------------------------------------------------------------------------
// K1: HMMA bf16 distance GEMM fused with per-token top-2.
// R5 configuration (best measured): 256 threads = 8 warps (4m x 2n), warp tile
// 64x64, 4-stage cp.async pipeline, XOR-swizzled smem, one sync per stage.
// ---------------------------------------------------------------------------
__global__ void __launch_bounds__(256, 1)
k_mma() {
    extern __shared__ char smem[];
    const uint sb  = smem_u32(smem);
    const uint sA  = sb;                       // 4 x 32KB
    const uint sB  = sb + NPIPE * ABYTES;      // 4 x 16KB

    const int tid  = threadIdx.x;
    const int lane = tid & 31;
    const int wid  = tid >> 5;
    const int wm   = wid & 3;       // m warp (4)
    const int wn   = wid >> 2;      // n warp (2)

    const int m0   = blockIdx.x * MTILE;
    const int nblk = blockIdx.y;
    const int n0   = nblk * NTILE;

    const __nv_bfloat16* gA = g_A + (ull)m0 * KTOT;
    const __nv_bfloat16* gB = g_B + (ull)n0 * KTOT;

    float c[4][8][4];
    #pragma unroll
    for (int i = 0; i < 4; i++)
        #pragma unroll
        for (int j = 0; j < 8; j++)
            #pragma unroll
            for (int r = 0; r < 4; r++) c[i][j][r] = 0.0f;

    // --- hoisted issue-side address components (tid-constant) ---
    const int ld_row = tid >> 3;
    const int ld_ch  = tid & 7;
    const uint ld_sw = (uint)((ld_ch ^ (ld_row & 7)) << 4);
    const uint dst_base = (uint)ld_row * 128u + ld_sw;
    const __nv_bfloat16* srcA0 = gA + (ull)ld_row * KTOT + ld_ch * 8;
    const __nv_bfloat16* srcB0 = gB + (ull)ld_row * KTOT + ld_ch * 8;

    // --- hoisted ldmatrix address components ---
    const int rowA = wm * 64 + (lane & 7) + ((lane >> 3) & 1) * 8;  // + i*16
    const int chA  = (lane >> 4);
    const int rowB = wn * 64 + (lane & 7) + ((lane >> 4) << 3);     // + nb*16
    const int chB  = (lane >> 3) & 1;
    uint colA[4], colB[4];
    #pragma unroll
    for (int ks = 0; ks < 4; ks++) {
        colA[ks] = (uint)(((ks * 2 + chA) ^ (rowA & 7)) << 4);
        colB[ks] = (uint)(((ks * 2 + chB) ^ (rowB & 7)) << 4);
    }
    uint rbaseA[4], rbaseB[4];
    #pragma unroll
    for (int i = 0; i < 4; i++) rbaseA[i] = (uint)(rowA + i * 16) * 128u;
    #pragma unroll
    for (int i = 0; i < 4; i++) rbaseB[i] = (uint)(rowB + i * 16) * 128u;

    // stage issuer: 8 A-chunks + 4 B-chunks of 16B per thread
    auto issue = [&](int s) {
        const int kb = s * KS;
        const uint bufA = sA + (uint)(s & (NPIPE - 1)) * ABYTES;
        const uint bufB = sB + (uint)(s & (NPIPE - 1)) * BBYTES;
        const __nv_bfloat16* sa  = srcA0 + kb;
        const __nv_bfloat16* sbp = srcB0 + kb;
        #pragma unroll
        for (int i = 0; i < 8; i++)
            CP16(bufA + dst_base + (uint)i * 4096u, sa + (ull)i * 32 * KTOT);
        #pragma unroll
        for (int i = 0; i < 4; i++)
            CP16(bufB + dst_base + (uint)i * 4096u, sbp + (ull)i * 32 * KTOT);
        CP_COMMIT();
    };

    issue(0); issue(1); issue(2);

    for (int s = 0; s < NSTAGES; s++) {
        if (s < NSTAGES - 2)       { CP_WAIT(2); }
        else if (s == NSTAGES - 2) { CP_WAIT(1); }
        else                       { CP_WAIT(0); }
        __syncthreads();

        const uint bufA = sA + (uint)(s & (NPIPE - 1)) * ABYTES;
        const uint bufB = sB + (uint)(s & (NPIPE - 1)) * BBYTES;

        #pragma unroll
        for (int ks = 0; ks < 4; ks++) {
            uint a[4][4];
            #pragma unroll
            for (int i = 0; i < 4; i++)
                LDSM4(a[i][0], a[i][1], a[i][2], a[i][3],
                      bufA + rbaseA[i] + colA[ks]);
            uint b[8][2];
            #pragma unroll
            for (int nb = 0; nb < 4; nb++) {
                uint r0, r1, r2, r3;
                LDSM4(r0, r1, r2, r3, bufB + rbaseB[nb] + colB[ks]);
                b[nb * 2][0] = r0;     b[nb * 2][1] = r1;
                b[nb * 2 + 1][0] = r2; b[nb * 2 + 1][1] = r3;
            }
            #pragma unroll
            for (int i = 0; i < 4; i++)
                #pragma unroll
                for (int j = 0; j < 8; j++)
                    MMA16816(c[i][j], a[i], b[j]);
        }
        if (s + 3 < NSTAGES) issue(s + 3);
    }

    // ---------------- epilogue: dist + top-2, no atomics --------------------
    __syncthreads();                // all warps done with smem tiles
    ull* sred = (ull*)smem;         // [256 rows][2 warp_n][2]

    float e2v[8][2];
    #pragma unroll
    for (int j = 0; j < 8; j++)
        #pragma unroll
        for (int q = 0; q < 2; q++)
            e2v[j][q] = g_e2[n0 + wn * 64 + j * 8 + (lane & 3) * 2 + q];

    #pragma unroll
    for (int i = 0; i < 4; i++) {
        #pragma unroll
        for (int h = 0; h < 2; h++) {
            const int m_local = wm * 64 + i * 16 + (lane >> 2) + h * 8;
            const float sx2 = g_sx2[m0 + m_local];
            ull b1 = 0ull, b2 = 0ull;
            #pragma unroll
            for (int j = 0; j < 8; j++) {
                #pragma unroll
                for (int q = 0; q < 2; q++) {
                    float dot  = c[i][j][h * 2 + q];
                    float dist = (sx2 - 2.0f * dot) + e2v[j][q];
                    const int n = n0 + wn * 64 + j * 8 + (lane & 3) * 2 + q;
                    uint u = __float_as_uint(dist);
                    uint m = (u & 0x80000000u) ? ~u : (u | 0x80000000u);
                    ull key = ((ull)(~m) << 32) | (uint)(KCODES - 1 - n);
                    if (key > b1)      { b2 = b1; b1 = key; }
                    else if (key > b2) { b2 = key; }
                }
            }
            #pragma unroll
            for (int sh = 1; sh <= 2; sh <<= 1) {
                ull o1 = __shfl_xor_sync(0xffffffffu, b1, sh);
                ull o2 = __shfl_xor_sync(0xffffffffu, b2, sh);
                ull n1 = umax(b1, o1);
                ull n2 = umax(umin(b1, o1), umax(b2, o2));
                b1 = n1; b2 = n2;
            }
            if ((lane & 3) == 0) {
                sred[(m_local * 2 + wn) * 2 + 0] = b1;
                sred[(m_local * 2 + wn) * 2 + 1] = b2;
            }
        }
    }
    __syncthreads();
    {
        const int row = tid;
        ull p1a = sred[(row * 2 + 0) * 2 + 0], p2a = sred[(row * 2 + 0) * 2 + 1];
        ull p1b = sred[(row * 2 + 1) * 2 + 0], p2b = sred[(row * 2 + 1) * 2 + 1];
        ull b1 = umax(p1a, p1b);
        ull b2 = umax(umin(p1a, p1b), umax(p2a, p2b));
        g_top1[(ull)(m0 + row) * NSPLITS + nblk] = b1;   // [token][split]
        g_top2[(ull)(m0 + row) * NSPLITS + nblk] = b2;
    }
}

// ---------------------------------------------------------------------------
// K2a: warp-per-token split merge + near-tie exact fp32 fixup (lane-parallel)
// ---------------------------------------------------------------------------
__global__ void k_assign(const float* __restrict__ z, const float* __restrict__ E,
                         float* __restrict__ out) {
    const int gtid = blockIdx.x * 256 + threadIdx.x;
    const int n    = gtid >> 5;          // token = warp
    const int lane = gtid & 31;
    if (n >= NTOK) return;

    const ull* t1p = g_top1 + (ull)n * NSPLITS;
    const ull* t2p = g_top2 + (ull)n * NSPLITS;
    ull b1 = 0ull, b2 = 0ull;
    #pragma unroll
    for (int r = 0; r < 2; r++) {
        int s = lane + r * 32;
        ull t1 = t1p[s], t2 = t2p[s];
        if (t1 > b1)      { b2 = b1; b1 = t1; }
        else if (t1 > b2) { b2 = t1; }
        if (t2 > b2)      { b2 = t2; }
    }
    #pragma unroll
    for (int sh = 16; sh >= 1; sh >>= 1) {
        ull o1 = __shfl_xor_sync(0xffffffffu, b1, sh);
        ull o2 = __shfl_xor_sync(0xffffffffu, b2, sh);
        ull n1 = umax(b1, o1);
        ull n2 = umax(umin(b1, o1), umax(b2, o2));
        b1 = n1; b2 = n2;
    }

    int i1 = (KCODES - 1) - (int)(uint)(b1 & 0xffffffffu);
    int i2 = (KCODES - 1) - (int)(uint)(b2 & 0xffffffffu);
    uint m1 = ~(uint)(b1 >> 32), m2 = ~(uint)(b2 >> 32);
    float d1 = __uint_as_float((m1 & 0x80000000u) ? (m1 & 0x7fffffffu) : ~m1);
    float d2 = __uint_as_float((m2 & 0x80000000u) ? (m2 & 0x7fffffffu) : ~m2);

    int idx = i1;
    if (d2 - d1 < 2e-4f) {
        // exact fp32 re-score, lane-parallel (8 dims/lane), bucketed like ref
        int b = n >> 10, hw = n & 1023;
        const float* zp  = z + b * DD * HW + hw;
        const float* ep1 = E + i1;
        const float* ep2 = E + i2;
        float dot1 = 0.0f, dot2 = 0.0f;
        #pragma unroll
        for (int t = 0; t < 8; t++) {
            int d = t * 32 + lane;
            float zv = zp[d * HW];
            dot1 = fmaf(zv, ep1[d * KCODES], dot1);
            dot2 = fmaf(zv, ep2[d * KCODES], dot2);
        }
        #pragma unroll
        for (int sh = 16; sh >= 1; sh >>= 1) {
            dot1 += __shfl_xor_sync(0xffffffffu, dot1, sh);
            dot2 += __shfl_xor_sync(0xffffffffu, dot2, sh);
        }
        float sx2 = g_sx2[n];
        float e1  = (sx2 - 2.0f * dot1) + g_e2[i1];
        float e2x = (sx2 - 2.0f * dot2) + g_e2[i2];
        if (e2x < e1 || (e2x == e1 && i2 < i1)) idx = i2;
    }
    if (lane == 0) {
        g_idx[n] = idx;
        out[OUT_IDX + n] = (float)idx;
        atomicAdd(&out[OUT_CS + idx], 1.0f);
    }
}

// ---------------------------------------------------------------------------
// K2b: gather quantized (NCHW), scatter dw, accumulate loss
// ---------------------------------------------------------------------------
__global__ void k_scatter(const float* __restrict__ z, const float* __restrict__ E,
                          float* __restrict__ out) {
    int tx = threadIdx.x & 31;
    int ty = threadIdx.x >> 5;
    int hw = blockIdx.x * 32 + tx;
    int d  = blockIdx.y * 8 + ty;
    int b  = blockIdx.z;

    int n   = b * HW + hw;
    int idx = g_idx[n];
    float q  = E[d * KCODES + idx];
    int   zi = (b * DD + d) * HW + hw;
    float zv = z[zi];
    out[OUT_Q + zi] = q;
    float diff = q - zv;
    atomicAdd(&out[OUT_DW + d * KCODES + idx], zv);

    __shared__ float red[256];
    red[threadIdx.x] = diff * diff;
    __syncthreads();
    #pragma unroll
    for (int s = 128; s > 0; s >>= 1) {
        if (threadIdx.x < s) red[threadIdx.x] += red[threadIdx.x + s];
        __syncthreads();
    }
    if (threadIdx.x == 0) atomicAdd(&g_loss, (double)red[0]);
}

// ---------------------------------------------------------------------------
// K3: loss + perplexity
// ---------------------------------------------------------------------------
__global__ void k_final(float* __restrict__ out) {
    __shared__ float red[256];
    int t = threadIdx.x;
    float s = 0.0f;
    for (int k = t; k < KCODES; k += 256) {
        float p = out[OUT_CS + k] * (1.0f / 8192.0f);
        s += p * logf(p + 1e-10f);
    }
    red[t] = s;
    __syncthreads();
    #pragma unroll
    for (int st = 128; st > 0; st >>= 1) {
        if (t < st) red[t] += red[t + st];
        __syncthreads();
    }
    if (t == 0) {
        out[OUT_PERP] = expf(-red[0]);
        out[OUT_LOSS] = (float)(0.25 * g_loss / 2097152.0);
    }
}

// ---------------------------------------------------------------------------
extern "C" void kernel_launch(void* const* d_in, const int* in_sizes, int n_in,
                              void* d_out, int out_size) {
    const float* z = (const float*)d_in[0];         // [8,256,32,32]
    const float* E = (const float*)d_in[1];         // [256,8192]
    float* out = (float*)d_out;

    cudaFuncSetAttribute(k_mma, cudaFuncAttributeMaxDynamicSharedMemorySize,
                         SMEM_DYN);

    k_prep   <<< 512, 256 >>>(z, E, out);
    k_mma    <<< dim3(NTOK / MTILE, NSPLITS), 256, SMEM_DYN >>>();
    k_assign <<< (NTOK * 32) / 256, 256 >>>(z, E, out);
    k_scatter<<< dim3(HW / 32, DD / 8, BATCH), 256 >>>(z, E, out);
    k_final  <<< 1, 256 >>>(out);
}

// round 8
// speedup vs baseline: 3.7415x; 1.2435x over previous
#include <cuda_runtime.h>
#include <cuda_bf16.h>
#include <math.h>

// Problem constants
#define DD      256
#define KCODES  8192
#define BATCH   8
#define HW      1024
#define NTOK    8192

// Output layout (flattened return tuple, in order)
#define OUT_Q     0
#define OUT_LOSS  2097152
#define OUT_PERP  2097153
#define OUT_IDX   2097154
#define OUT_DW    2105346
#define OUT_CS    4202498

// GEMM config: C[8192 tok, 8192 codes] = A[.,768] * B[.,768]^T  (bf16x3 split)
#define KTOT    768
#define MTILE   256
#define NTILE   128
#define KS      64
#define NSTAGES 12                    // 768/64 per n-block
#define GSTAGES 24                    // 2 n-blocks per CTA, continuous pipeline
#define NPIPE   4                     // cp.async pipeline depth
#define NSPLITS (KCODES / NTILE)      // 64
#define ABYTES  32768                 // per-stage A buffer
#define BBYTES  16384                 // per-stage B buffer
#define SM_RED  (NPIPE * (ABYTES + BBYTES))    // 192KB: sred region after tiles
#define SMEM_DYN (SM_RED + 8192)               // + 8KB reduction scratch

typedef unsigned long long ull;
typedef unsigned int uint;

// ---------------- device scratch (no allocation allowed) --------------------
__device__ __nv_bfloat16 g_A[NTOK   * KTOT];  // [tok ][xh(256)|xh(256)|xl(256)]
__device__ __nv_bfloat16 g_B[KCODES * KTOT];  // [code][eh(256)|el(256)|eh(256)]
__device__ float  g_e2[KCODES];
__device__ float  g_sx2[NTOK];
__device__ ull    g_top1[NTOK * NSPLITS];     // [token][split]  (coalesced merge)
__device__ ull    g_top2[NTOK * NSPLITS];
__device__ int    g_idx[NTOK];
__device__ double g_loss;

// ---------------- PTX helpers (all plain-sm_100 legal) ----------------------
__device__ __forceinline__ uint smem_u32(const void* p) {
    uint a;
    asm("{ .reg .u64 t; cvta.to.shared.u64 t, %1; cvt.u32.u64 %0, t; }"
        : "=r"(a) : "l"(p));
    return a;
}
#define CP16(dst, src) \
    asm volatile("cp.async.cg.shared.global [%0], [%1], 16;" :: "r"(dst), "l"(src))
#define CP_COMMIT() asm volatile("cp.async.commit_group;")
#define CP_WAIT(n)  asm volatile("cp.async.wait_group %0;" :: "n"(n))

#define LDSM4(r0, r1, r2, r3, a) \
    asm volatile("ldmatrix.sync.aligned.m8n8.x4.shared.b16 {%0,%1,%2,%3}, [%4];" \
        : "=r"(r0), "=r"(r1), "=r"(r2), "=r"(r3) : "r"(a))

#define MMA16816(c, a, b) \
    asm volatile("mma.sync.aligned.m16n8k16.row.col.f32.bf16.bf16.f32 " \
        "{%0,%1,%2,%3}, {%4,%5,%6,%7}, {%8,%9}, {%0,%1,%2,%3};" \
        : "+f"((c)[0]), "+f"((c)[1]), "+f"((c)[2]), "+f"((c)[3]) \
        : "r"((a)[0]), "r"((a)[1]), "r"((a)[2]), "r"((a)[3]), \
          "r"((b)[0]), "r"((b)[1]))

__device__ __forceinline__ ull umax(ull a, ull b) { return a > b ? a : b; }
__device__ __forceinline__ ull umin(ull a, ull b) { return a < b ? a : b; }

// ---------------------------------------------------------------------------
// K_prep (fused init + norms + transpose/split, vectorized bf16 stores):
//   Blocks 0..255:   z -> g_A (32 tokens each) + g_sx2
//   Blocks 256..511: E -> g_B (32 codes each)  + g_e2
// ---------------------------------------------------------------------------
__global__ void k_prep(const float* __restrict__ z, const float* __restrict__ E,
                       float* __restrict__ out) {
    __shared__ float st[32 * 264];
    const int tid = threadIdx.x;
    const bool isB = blockIdx.x >= 256;
    const int n0 = (isB ? (blockIdx.x - 256) : blockIdx.x) * 32;

    // zero dw + cluster_size (2105344 floats = 1052672 float2, 8B-aligned)
    {
        const float2 z2 = make_float2(0.0f, 0.0f);
        float2* dst2 = (float2*)(out + OUT_DW);
        for (int i = blockIdx.x * 256 + tid; i < 1052672; i += 512 * 256)
            dst2[i] = z2;
        if (blockIdx.x == 0 && tid == 0) g_loss = 0.0;
    }

    // load 32 rows x 256 dims into smem (transposed)
    for (int i = tid; i < 32 * 256; i += 256) {
        int k = i >> 5, nl = i & 31;
        float v;
        if (isB) v = E[k * KCODES + n0 + nl];
        else {
            int b = n0 >> 10, hw0 = n0 & 1023;
            v = z[(b * DD + k) * HW + hw0 + nl];
        }
        st[nl * 264 + k] = v;
    }
    __syncthreads();

    // norms: one thread per row, sequential fp32 over d (bit-identical to ref path)
    if (tid < 32) {
        float s = 0.0f;
        #pragma unroll 8
        for (int d = 0; d < DD; d++) { float v = st[tid * 264 + d]; s += v * v; }
        if (isB) g_e2[n0 + tid] = s;
        else     g_sx2[n0 + tid] = s;
    }

    // bf16 hi/lo split, packed stores:  A row [xh|xh|xl],  B row [eh|el|eh]
    __nv_bfloat16* dst = isB ? g_B : g_A;
    const int nl = tid >> 3;
    const int jb = (tid & 7) * 32;
    __nv_bfloat16* rowp = dst + (ull)(n0 + nl) * KTOT;

    uint hwv[16], lwv[16];
    #pragma unroll
    for (int t = 0; t < 16; t++) {
        float v0 = st[nl * 264 + jb + 2 * t];
        float v1 = st[nl * 264 + jb + 2 * t + 1];
        __nv_bfloat16 h0 = __float2bfloat16(v0);
        __nv_bfloat16 h1 = __float2bfloat16(v1);
        __nv_bfloat16 l0 = __float2bfloat16(v0 - __bfloat162float(h0));
        __nv_bfloat16 l1 = __float2bfloat16(v1 - __bfloat162float(h1));
        hwv[t] = (uint)__bfloat16_as_ushort(h0) | ((uint)__bfloat16_as_ushort(h1) << 16);
        lwv[t] = (uint)__bfloat16_as_ushort(l0) | ((uint)__bfloat16_as_ushort(l1) << 16);
    }
    uint4* p0 = (uint4*)(rowp + jb);            // hi
    uint4* p1 = (uint4*)(rowp + 256 + jb);      // B: lo,  A: hi
    uint4* p2 = (uint4*)(rowp + 512 + jb);      // B: hi,  A: lo
    #pragma unroll
    for (int t = 0; t < 4; t++) {
        uint4 hv = make_uint4(hwv[4*t], hwv[4*t+1], hwv[4*t+2], hwv[4*t+3]);
        uint4 lv = make_uint4(lwv[4*t], lwv[4*t+1], lwv[4*t+2], lwv[4*t+3]);
        p0[t] = hv;
        p1[t] = isB ? lv : hv;
        p2[t] = isB ? hv : lv;
    }
}

// ---------------------------------------------------------------------------
// K1: HMMA bf16 distance GEMM fused with per-token top-2.
// 256 threads = 8 warps (4m x 2n), warp tile 64x64. Each CTA processes TWO
// adjacent n-blocks with ONE continuous 24-stage cp.async pipeline (never
// drained); the nb=0 epilogue overlaps nb=1 prefetch. sred lives in its own
// smem region so it can't clobber in-flight pipeline buffers.
// ---------------------------------------------------------------------------
__global__ void __launch_bounds__(256, 1)
k_mma() {
    extern __shared__ char smem[];
    const uint sb  = smem_u32(smem);
    const uint sA  = sb;                       // 4 x 32KB
    const uint sB  = sb + NPIPE * ABYTES;      // 4 x 16KB
    ull* sred = (ull*)(smem + SM_RED);         // 8KB, separate from tiles

    const int tid  = threadIdx.x;
    const int lane = tid & 31;
    const int wid  = tid >> 5;
    const int wm   = wid & 3;       // m warp (4)
    const int wn   = wid >> 2;      // n warp (2)

    const int m0   = blockIdx.x * MTILE;
    const int pair = blockIdx.y;                 // 0..31
    const int n0p  = pair * (2 * NTILE);         // first of two n-blocks

    const __nv_bfloat16* gA = g_A + (ull)m0 * KTOT;
    const __nv_bfloat16* gB = g_B + (ull)n0p * KTOT;

    // --- hoisted issue-side address components (tid-constant) ---
    const int ld_row = tid >> 3;
    const int ld_ch  = tid & 7;
    const uint ld_sw = (uint)((ld_ch ^ (ld_row & 7)) << 4);
    const uint dst_base = (uint)ld_row * 128u + ld_sw;
    const __nv_bfloat16* srcA0 = gA + (ull)ld_row * KTOT + ld_ch * 8;
    const __nv_bfloat16* srcB0 = gB + (ull)ld_row * KTOT + ld_ch * 8;

    // --- hoisted ldmatrix address components ---
    const int rowA = wm * 64 + (lane & 7) + ((lane >> 3) & 1) * 8;  // + i*16
    const int chA  = (lane >> 4);
    const int rowB = wn * 64 + (lane & 7) + ((lane >> 4) << 3);     // + nb*16
    const int chB  = (lane >> 3) & 1;
    uint colA[4], colB[4];
    #pragma unroll
    for (int ks = 0; ks < 4; ks++) {
        colA[ks] = (uint)(((ks * 2 + chA) ^ (rowA & 7)) << 4);
        colB[ks] = (uint)(((ks * 2 + chB) ^ (rowB & 7)) << 4);
    }
    uint rbaseA[4], rbaseB[4];
    #pragma unroll
    for (int i = 0; i < 4; i++) rbaseA[i] = (uint)(rowA + i * 16) * 128u;
    #pragma unroll
    for (int i = 0; i < 4; i++) rbaseB[i] = (uint)(rowB + i * 16) * 128u;

    // global-stage issuer: gs in [0,24), nb = gs/12, k-stage = gs%12
    auto issue = [&](int gs) {
        const int nb = (gs >= NSTAGES) ? 1 : 0;
        const int kb = (gs - nb * NSTAGES) * KS;
        const uint bufA = sA + (uint)(gs & (NPIPE - 1)) * ABYTES;
        const uint bufB = sB + (uint)(gs & (NPIPE - 1)) * BBYTES;
        const __nv_bfloat16* sa  = srcA0 + kb;
        const __nv_bfloat16* sbp = srcB0 + (ull)nb * NTILE * KTOT + kb;
        #pragma unroll
        for (int i = 0; i < 8; i++)
            CP16(bufA + dst_base + (uint)i * 4096u, sa + (ull)i * 32 * KTOT);
        #pragma unroll
        for (int i = 0; i < 4; i++)
            CP16(bufB + dst_base + (uint)i * 4096u, sbp + (ull)i * 32 * KTOT);
        CP_COMMIT();
    };

    issue(0); issue(1); issue(2);

    float c[4][8][4];

    for (int nb = 0; nb < 2; nb++) {
        #pragma unroll
        for (int i = 0; i < 4; i++)
            #pragma unroll
            for (int j = 0; j < 8; j++)
                #pragma unroll
                for (int r = 0; r < 4; r++) c[i][j][r] = 0.0f;

        for (int s = 0; s < NSTAGES; s++) {
            const int gs = nb * NSTAGES + s;
            if (gs < GSTAGES - 2)       { CP_WAIT(2); }
            else if (gs == GSTAGES - 2) { CP_WAIT(1); }
            else                        { CP_WAIT(0); }
            __syncthreads();

            const uint bufA = sA + (uint)(gs & (NPIPE - 1)) * ABYTES;
            const uint bufB = sB + (uint)(gs & (NPIPE - 1)) * BBYTES;

            #pragma unroll
            for (int ks = 0; ks < 4; ks++) {
                uint a[4][4];
                #pragma unroll
                for (int i = 0; i < 4; i++)
                    LDSM4(a[i][0], a[i][1], a[i][2], a[i][3],
                          bufA + rbaseA[i] + colA[ks]);
                uint b[8][2];
                #pragma unroll
                for (int nbm = 0; nbm < 4; nbm++) {
                    uint r0, r1, r2, r3;
                    LDSM4(r0, r1, r2, r3, bufB + rbaseB[nbm] + colB[ks]);
                    b[nbm * 2][0] = r0;     b[nbm * 2][1] = r1;
                    b[nbm * 2 + 1][0] = r2; b[nbm * 2 + 1][1] = r3;
                }
                #pragma unroll
                for (int i = 0; i < 4; i++)
                    #pragma unroll
                    for (int j = 0; j < 8; j++)
                        MMA16816(c[i][j], a[i], b[j]);
            }
            if (gs + 3 < GSTAGES) issue(gs + 3);
        }

        // ------------- epilogue nb: dist + top-2 (overlaps nb=1 prefetch) ----
        const int n0 = n0p + nb * NTILE;
        __syncthreads();            // prior epilogue readers done with sred

        float e2v[8][2];
        #pragma unroll
        for (int j = 0; j < 8; j++)
            #pragma unroll
            for (int q = 0; q < 2; q++)
                e2v[j][q] = g_e2[n0 + wn * 64 + j * 8 + (lane & 3) * 2 + q];

        #pragma unroll
        for (int i = 0; i < 4; i++) {
            #pragma unroll
            for (int h = 0; h < 2; h++) {
                const int m_local = wm * 64 + i * 16 + (lane >> 2) + h * 8;
                const float sx2 = g_sx2[m0 + m_local];
                ull b1 = 0ull, b2 = 0ull;
                #pragma unroll
                for (int j = 0; j < 8; j++) {
                    #pragma unroll
                    for (int q = 0; q < 2; q++) {
                        float dot  = c[i][j][h * 2 + q];
                        float dist = (sx2 - 2.0f * dot) + e2v[j][q];
                        const int n = n0 + wn * 64 + j * 8 + (lane & 3) * 2 + q;
                        uint u = __float_as_uint(dist);
                        uint m = (u & 0x80000000u) ? ~u : (u | 0x80000000u);
                        ull key = ((ull)(~m) << 32) | (uint)(KCODES - 1 - n);
                        if (key > b1)      { b2 = b1; b1 = key; }
                        else if (key > b2) { b2 = key; }
                    }
                }
                #pragma unroll
                for (int sh = 1; sh <= 2; sh <<= 1) {
                    ull o1 = __shfl_xor_sync(0xffffffffu, b1, sh);
                    ull o2 = __shfl_xor_sync(0xffffffffu, b2, sh);
                    ull n1 = umax(b1, o1);
                    ull n2 = umax(umin(b1, o1), umax(b2, o2));
                    b1 = n1; b2 = n2;
                }
                if ((lane & 3) == 0) {
                    sred[(m_local * 2 + wn) * 2 + 0] = b1;
                    sred[(m_local * 2 + wn) * 2 + 1] = b2;
                }
            }
        }
        __syncthreads();
        {
            const int row = tid;
            ull p1a = sred[(row * 2 + 0) * 2 + 0], p2a = sred[(row * 2 + 0) * 2 + 1];
            ull p1b = sred[(row * 2 + 1) * 2 + 0], p2b = sred[(row * 2 + 1) * 2 + 1];
            ull b1 = umax(p1a, p1b);
            ull b2 = umax(umin(p1a, p1b), umax(p2a, p2b));
            const int nblk = pair * 2 + nb;
            g_top1[(ull)(m0 + row) * NSPLITS + nblk] = b1;   // [token][split]
            g_top2[(ull)(m0 + row) * NSPLITS + nblk] = b2;
        }
    }
}

// ---------------------------------------------------------------------------
// K2a: warp-per-token split merge + near-tie exact fp32 fixup (lane-parallel)
// ---------------------------------------------------------------------------
__global__ void k_assign(const float* __restrict__ z, const float* __restrict__ E,
                         float* __restrict__ out) {
    const int gtid = blockIdx.x * 256 + threadIdx.x;
    const int n    = gtid >> 5;          // token = warp
    const int lane = gtid & 31;
    if (n >= NTOK) return;

    const ull* t1p = g_top1 + (ull)n * NSPLITS;
    const ull* t2p = g_top2 + (ull)n * NSPLITS;
    ull b1 = 0ull, b2 = 0ull;
    #pragma unroll
    for (int r = 0; r < 2; r++) {
        int s = lane + r * 32;
        ull t1 = t1p[s], t2 = t2p[s];
        if (t1 > b1)      { b2 = b1; b1 = t1; }
        else if (t1 > b2) { b2 = t1; }
        if (t2 > b2)      { b2 = t2; }
    }
    #pragma unroll
    for (int sh = 16; sh >= 1; sh >>= 1) {
        ull o1 = __shfl_xor_sync(0xffffffffu, b1, sh);
        ull o2 = __shfl_xor_sync(0xffffffffu, b2, sh);
        ull n1 = umax(b1, o1);
        ull n2 = umax(umin(b1, o1), umax(b2, o2));
        b1 = n1; b2 = n2;
    }

    int i1 = (KCODES - 1) - (int)(uint)(b1 & 0xffffffffu);
    int i2 = (KCODES - 1) - (int)(uint)(b2 & 0xffffffffu);
    uint m1 = ~(uint)(b1 >> 32), m2 = ~(uint)(b2 >> 32);
    float d1 = __uint_as_float((m1 & 0x80000000u) ? (m1 & 0x7fffffffu) : ~m1);
    float d2 = __uint_as_float((m2 & 0x80000000u) ? (m2 & 0x7fffffffu) : ~m2);

    int idx = i1;
    if (d2 - d1 < 2e-4f) {
        // exact fp32 re-score, lane-parallel (8 dims/lane), bucketed like ref
        int b = n >> 10, hw = n & 1023;
        const float* zp  = z + b * DD * HW + hw;
        const float* ep1 = E + i1;
        const float* ep2 = E + i2;
        float dot1 = 0.0f, dot2 = 0.0f;
        #pragma unroll
        for (int t = 0; t < 8; t++) {
            int d = t * 32 + lane;
            float zv = zp[d * HW];
            dot1 = fmaf(zv, ep1[d * KCODES], dot1);
            dot2 = fmaf(zv, ep2[d * KCODES], dot2);
        }
        #pragma unroll
        for (int sh = 16; sh >= 1; sh >>= 1) {
            dot1 += __shfl_xor_sync(0xffffffffu, dot1, sh);
            dot2 += __shfl_xor_sync(0xffffffffu, dot2, sh);
        }
        float sx2 = g_sx2[n];
        float e1  = (sx2 - 2.0f * dot1) + g_e2[i1];
        float e2x = (sx2 - 2.0f * dot2) + g_e2[i2];
        if (e2x < e1 || (e2x == e1 && i2 < i1)) idx = i2;
    }
    if (lane == 0) {
        g_idx[n] = idx;
        out[OUT_IDX + n] = (float)idx;
        atomicAdd(&out[OUT_CS + idx], 1.0f);
    }
}

// ---------------------------------------------------------------------------
// K2b: gather quantized (NCHW), scatter dw, accumulate loss
// ---------------------------------------------------------------------------
__global__ void k_scatter(const float* __restrict__ z, const float* __restrict__ E,
                          float* __restrict__ out) {
    int tx = threadIdx.x & 31;
    int ty = threadIdx.x >> 5;
    int hw = blockIdx.x * 32 + tx;
    int d  = blockIdx.y * 8 + ty;
    int b  = blockIdx.z;

    int n   = b * HW + hw;
    int idx = g_idx[n];
    float q  = E[d * KCODES + idx];
    int   zi = (b * DD + d) * HW + hw;
    float zv = z[zi];
    out[OUT_Q + zi] = q;
    float diff = q - zv;
    atomicAdd(&out[OUT_DW + d * KCODES + idx], zv);

    __shared__ float red[256];
    red[threadIdx.x] = diff * diff;
    __syncthreads();
    #pragma unroll
    for (int s = 128; s > 0; s >>= 1) {
        if (threadIdx.x < s) red[threadIdx.x] += red[threadIdx.x + s];
        __syncthreads();
    }
    if (threadIdx.x == 0) atomicAdd(&g_loss, (double)red[0]);
}

// ---------------------------------------------------------------------------
// K3: loss + perplexity
// ---------------------------------------------------------------------------
__global__ void k_final(float* __restrict__ out) {
    __shared__ float red[256];
    int t = threadIdx.x;
    float s = 0.0f;
    for (int k = t; k < KCODES; k += 256) {
        float p = out[OUT_CS + k] * (1.0f / 8192.0f);
        s += p * logf(p + 1e-10f);
    }
    red[t] = s;
    __syncthreads();
    #pragma unroll
    for (int st = 128; st > 0; st >>= 1) {
        if (t < st) red[t] += red[t + st];
        __syncthreads();
    }
    if (t == 0) {
        out[OUT_PERP] = expf(-red[0]);
        out[OUT_LOSS] = (float)(0.25 * g_loss / 2097152.0);
    }
}

// ---------------------------------------------------------------------------
extern "C" void kernel_launch(void* const* d_in, const int* in_sizes, int n_in,
                              void* d_out, int out_size) {
    const float* z = (const float*)d_in[0];         // [8,256,32,32]
    const float* E = (const float*)d_in[1];         // [256,8192]
    float* out = (float*)d_out;

    cudaFuncSetAttribute(k_mma, cudaFuncAttributeMaxDynamicSharedMemorySize,
                         SMEM_DYN);

    k_prep   <<< 512, 256 >>>(z, E, out);
    k_mma    <<< dim3(NTOK / MTILE, NSPLITS / 2), 256, SMEM_DYN >>>();
    k_assign <<< (NTOK * 32) / 256, 256 >>>(z, E, out);
    k_scatter<<< dim3(HW / 32, DD / 8, BATCH), 256 >>>(z, E, out);
    k_final  <<< 1, 256 >>>(out);
}

// round 9
// speedup vs baseline: 4.1881x; 1.1194x over previous
#include <cuda_runtime.h>
#include <cuda_bf16.h>
#include <math.h>

// Problem constants
#define DD      256
#define KCODES  8192
#define BATCH   8
#define HW      1024
#define NTOK    8192

// Output layout (flattened return tuple, in order)
#define OUT_Q     0
#define OUT_LOSS  2097152
#define OUT_PERP  2097153
#define OUT_IDX   2097154
#define OUT_DW    2105346
#define OUT_CS    4202498

// GEMM config: C[8192 tok, 8192 codes] = A[.,768] * B[.,768]^T  (bf16x3 split)
#define KTOT    768
#define MTILE   128
#define NTILE   128
#define KS      64
#define NSTAGES 12                    // 768/64
#define NPIPE   3                     // cp.async pipeline depth
#define NSPLITS (KCODES / NTILE)      // 64
#define ABYTES  16384                 // per-stage A buffer (128 x 128B)
#define BBYTES  16384                 // per-stage B buffer
#define SM_RED  (NPIPE * (ABYTES + BBYTES))    // 98304: sred after tiles
#define SMEM_DYN (SM_RED + 4096)               // 100KB/CTA -> 2 CTAs/SM

typedef unsigned long long ull;
typedef unsigned int uint;

// ---------------- device scratch (no allocation allowed) --------------------
__device__ __nv_bfloat16 g_A[NTOK   * KTOT];  // [tok ][xh(256)|xh(256)|xl(256)]
__device__ __nv_bfloat16 g_B[KCODES * KTOT];  // [code][eh(256)|el(256)|eh(256)]
__device__ float  g_e2[KCODES];
__device__ float  g_sx2[NTOK];
__device__ ull    g_top1[NTOK * NSPLITS];     // [token][split]  (coalesced merge)
__device__ ull    g_top2[NTOK * NSPLITS];
__device__ int    g_idx[NTOK];
__device__ double g_loss;

// ---------------- PTX helpers (all plain-sm_100 legal) ----------------------
__device__ __forceinline__ uint smem_u32(const void* p) {
    uint a;
    asm("{ .reg .u64 t; cvta.to.shared.u64 t, %1; cvt.u32.u64 %0, t; }"
        : "=r"(a) : "l"(p));
    return a;
}
#define CP16(dst, src) \
    asm volatile("cp.async.cg.shared.global [%0], [%1], 16;" :: "r"(dst), "l"(src))
#define CP_COMMIT() asm volatile("cp.async.commit_group;")
#define CP_WAIT(n)  asm volatile("cp.async.wait_group %0;" :: "n"(n))

#define LDSM4(r0, r1, r2, r3, a) \
    asm volatile("ldmatrix.sync.aligned.m8n8.x4.shared.b16 {%0,%1,%2,%3}, [%4];" \
        : "=r"(r0), "=r"(r1), "=r"(r2), "=r"(r3) : "r"(a))

#define MMA16816(c, a, b) \
    asm volatile("mma.sync.aligned.m16n8k16.row.col.f32.bf16.bf16.f32 " \
        "{%0,%1,%2,%3}, {%4,%5,%6,%7}, {%8,%9}, {%0,%1,%2,%3};" \
        : "+f"((c)[0]), "+f"((c)[1]), "+f"((c)[2]), "+f"((c)[3]) \
        : "r"((a)[0]), "r"((a)[1]), "r"((a)[2]), "r"((a)[3]), \
          "r"((b)[0]), "r"((b)[1]))

__device__ __forceinline__ ull umax(ull a, ull b) { return a > b ? a : b; }
__device__ __forceinline__ ull umin(ull a, ull b) { return a < b ? a : b; }

// ---------------------------------------------------------------------------
// K_prep (fused init + norms + transpose/split, vectorized bf16 stores):
//   Blocks 0..255:   z -> g_A (32 tokens each) + g_sx2
//   Blocks 256..511: E -> g_B (32 codes each)  + g_e2
// ---------------------------------------------------------------------------
__global__ void k_prep(const float* __restrict__ z, const float* __restrict__ E,
                       float* __restrict__ out) {
    __shared__ float st[32 * 264];
    const int tid = threadIdx.x;
    const bool isB = blockIdx.x >= 256;
    const int n0 = (isB ? (blockIdx.x - 256) : blockIdx.x) * 32;

    // zero dw + cluster_size (2105344 floats = 1052672 float2, 8B-aligned)
    {
        const float2 z2 = make_float2(0.0f, 0.0f);
        float2* dst2 = (float2*)(out + OUT_DW);
        for (int i = blockIdx.x * 256 + tid; i < 1052672; i += 512 * 256)
            dst2[i] = z2;
        if (blockIdx.x == 0 && tid == 0) g_loss = 0.0;
    }

    // load 32 rows x 256 dims into smem (transposed)
    for (int i = tid; i < 32 * 256; i += 256) {
        int k = i >> 5, nl = i & 31;
        float v;
        if (isB) v = E[k * KCODES + n0 + nl];
        else {
            int b = n0 >> 10, hw0 = n0 & 1023;
            v = z[(b * DD + k) * HW + hw0 + nl];
        }
        st[nl * 264 + k] = v;
    }
    __syncthreads();

    // norms: one thread per row, sequential fp32 over d (bit-identical path)
    if (tid < 32) {
        float s = 0.0f;
        #pragma unroll 8
        for (int d = 0; d < DD; d++) { float v = st[tid * 264 + d]; s += v * v; }
        if (isB) g_e2[n0 + tid] = s;
        else     g_sx2[n0 + tid] = s;
    }

    // bf16 hi/lo split, packed stores:  A row [xh|xh|xl],  B row [eh|el|eh]
    __nv_bfloat16* dst = isB ? g_B : g_A;
    const int nl = tid >> 3;
    const int jb = (tid & 7) * 32;
    __nv_bfloat16* rowp = dst + (ull)(n0 + nl) * KTOT;

    uint hwv[16], lwv[16];
    #pragma unroll
    for (int t = 0; t < 16; t++) {
        float v0 = st[nl * 264 + jb + 2 * t];
        float v1 = st[nl * 264 + jb + 2 * t + 1];
        __nv_bfloat16 h0 = __float2bfloat16(v0);
        __nv_bfloat16 h1 = __float2bfloat16(v1);
        __nv_bfloat16 l0 = __float2bfloat16(v0 - __bfloat162float(h0));
        __nv_bfloat16 l1 = __float2bfloat16(v1 - __bfloat162float(h1));
        hwv[t] = (uint)__bfloat16_as_ushort(h0) | ((uint)__bfloat16_as_ushort(h1) << 16);
        lwv[t] = (uint)__bfloat16_as_ushort(l0) | ((uint)__bfloat16_as_ushort(l1) << 16);
    }
    uint4* p0 = (uint4*)(rowp + jb);            // hi
    uint4* p1 = (uint4*)(rowp + 256 + jb);      // B: lo,  A: hi
    uint4* p2 = (uint4*)(rowp + 512 + jb);      // B: hi,  A: lo
    #pragma unroll
    for (int t = 0; t < 4; t++) {
        uint4 hv = make_uint4(hwv[4*t], hwv[4*t+1], hwv[4*t+2], hwv[4*t+3]);
        uint4 lv = make_uint4(lwv[4*t], lwv[4*t+1], lwv[4*t+2], lwv[4*t+3]);
        p0[t] = hv;
        p1[t] = isB ? lv : hv;
        p2[t] = isB ? hv : lv;
    }
}

// ---------------------------------------------------------------------------
// K1: HMMA bf16 distance GEMM fused with per-token top-2.
// CTA tile 128x128, 128 threads = 4 warps (2m x 2n), warp tile 64x64 (the
// proven LDSM/MMA ratio). 3-stage cp.async pipeline, 100KB smem -> TWO CTAs
// co-resident per SM, so one CTA's barriers/prolog hide under the other's
// MMAs. Grid (64 m-tiles, 64 n-blocks) = 4096 CTAs (~1% wave tail).
// ---------------------------------------------------------------------------
__global__ void __launch_bounds__(128, 2)
k_mma() {
    extern __shared__ char smem[];
    const uint sb  = smem_u32(smem);
    const uint sA  = sb;                       // 3 x 16KB
    const uint sB  = sb + NPIPE * ABYTES;      // 3 x 16KB
    ull* sred = (ull*)(smem + SM_RED);         // 4KB, separate from tiles

    const int tid  = threadIdx.x;
    const int lane = tid & 31;
    const int wid  = tid >> 5;      // 0..3
    const int wm   = wid & 1;       // m warp (2): 64 rows each
    const int wn   = wid >> 1;      // n warp (2): 64 cols each

    const int m0   = blockIdx.x * MTILE;
    const int nblk = blockIdx.y;
    const int n0   = nblk * NTILE;

    const __nv_bfloat16* gA = g_A + (ull)m0 * KTOT;
    const __nv_bfloat16* gB = g_B + (ull)n0 * KTOT;

    float c[4][8][4];
    #pragma unroll
    for (int i = 0; i < 4; i++)
        #pragma unroll
        for (int j = 0; j < 8; j++)
            #pragma unroll
            for (int r = 0; r < 4; r++) c[i][j][r] = 0.0f;

    // --- hoisted issue-side address components (tid-constant) ---
    // 128 threads: rows (tid>>3) + i*16, i in 0..7; chunk tid&7
    const int ld_row = tid >> 3;           // 0..15
    const int ld_ch  = tid & 7;
    const uint ld_sw = (uint)((ld_ch ^ (ld_row & 7)) << 4);
    const uint dst_base = (uint)ld_row * 128u + ld_sw;
    const __nv_bfloat16* srcA0 = gA + (ull)ld_row * KTOT + ld_ch * 8;
    const __nv_bfloat16* srcB0 = gB + (ull)ld_row * KTOT + ld_ch * 8;

    // --- hoisted ldmatrix address components ---
    const int rowA = wm * 64 + (lane & 7) + ((lane >> 3) & 1) * 8;  // + i*16
    const int chA  = (lane >> 4);
    const int rowB = wn * 64 + (lane & 7) + ((lane >> 4) << 3);     // + nb*16
    const int chB  = (lane >> 3) & 1;
    uint colA[4], colB[4];
    #pragma unroll
    for (int ks = 0; ks < 4; ks++) {
        colA[ks] = (uint)(((ks * 2 + chA) ^ (rowA & 7)) << 4);
        colB[ks] = (uint)(((ks * 2 + chB) ^ (rowB & 7)) << 4);
    }
    uint rbaseA[4], rbaseB[4];
    #pragma unroll
    for (int i = 0; i < 4; i++) rbaseA[i] = (uint)(rowA + i * 16) * 128u;
    #pragma unroll
    for (int i = 0; i < 4; i++) rbaseB[i] = (uint)(rowB + i * 16) * 128u;

    // stage issuer: 8 A-chunks + 8 B-chunks of 16B per thread (128 threads)
    auto issue = [&](int s, int buf) {
        const int kb = s * KS;
        const uint bufA = sA + (uint)buf * ABYTES;
        const uint bufB = sB + (uint)buf * BBYTES;
        const __nv_bfloat16* sa  = srcA0 + kb;
        const __nv_bfloat16* sbp = srcB0 + kb;
        #pragma unroll
        for (int i = 0; i < 8; i++)
            CP16(bufA + dst_base + (uint)i * 2048u, sa + (ull)i * 16 * KTOT);
        #pragma unroll
        for (int i = 0; i < 8; i++)
            CP16(bufB + dst_base + (uint)i * 2048u, sbp + (ull)i * 16 * KTOT);
        CP_COMMIT();
    };

    issue(0, 0); issue(1, 1);

    int buf = 0;
    for (int s = 0; s < NSTAGES; s++) {
        if (s < NSTAGES - 1) { CP_WAIT(1); } else { CP_WAIT(0); }
        __syncthreads();

        const uint bufA = sA + (uint)buf * ABYTES;
        const uint bufB = sB + (uint)buf * BBYTES;

        #pragma unroll
        for (int ks = 0; ks < 4; ks++) {
            uint a[4][4];
            #pragma unroll
            for (int i = 0; i < 4; i++)
                LDSM4(a[i][0], a[i][1], a[i][2], a[i][3],
                      bufA + rbaseA[i] + colA[ks]);
            uint b[8][2];
            #pragma unroll
            for (int nb = 0; nb < 4; nb++) {
                uint r0, r1, r2, r3;
                LDSM4(r0, r1, r2, r3, bufB + rbaseB[nb] + colB[ks]);
                b[nb * 2][0] = r0;     b[nb * 2][1] = r1;
                b[nb * 2 + 1][0] = r2; b[nb * 2 + 1][1] = r3;
            }
            #pragma unroll
            for (int i = 0; i < 4; i++)
                #pragma unroll
                for (int j = 0; j < 8; j++)
                    MMA16816(c[i][j], a[i], b[j]);
        }
        if (s + 2 < NSTAGES) {
            int nbuf = buf + 2; if (nbuf >= NPIPE) nbuf -= NPIPE;
            issue(s + 2, nbuf);
        }
        if (++buf == NPIPE) buf = 0;
    }

    // ---------------- epilogue: dist + top-2, no atomics --------------------
    float e2v[8][2];
    #pragma unroll
    for (int j = 0; j < 8; j++)
        #pragma unroll
        for (int q = 0; q < 2; q++)
            e2v[j][q] = g_e2[n0 + wn * 64 + j * 8 + (lane & 3) * 2 + q];

    #pragma unroll
    for (int i = 0; i < 4; i++) {
        #pragma unroll
        for (int h = 0; h < 2; h++) {
            const int m_local = wm * 64 + i * 16 + (lane >> 2) + h * 8;
            const float sx2 = g_sx2[m0 + m_local];
            ull b1 = 0ull, b2 = 0ull;
            #pragma unroll
            for (int j = 0; j < 8; j++) {
                #pragma unroll
                for (int q = 0; q < 2; q++) {
                    float dot  = c[i][j][h * 2 + q];
                    float dist = (sx2 - 2.0f * dot) + e2v[j][q];
                    const int n = n0 + wn * 64 + j * 8 + (lane & 3) * 2 + q;
                    uint u = __float_as_uint(dist);
                    uint m = (u & 0x80000000u) ? ~u : (u | 0x80000000u);
                    ull key = ((ull)(~m) << 32) | (uint)(KCODES - 1 - n);
                    if (key > b1)      { b2 = b1; b1 = key; }
                    else if (key > b2) { b2 = key; }
                }
            }
            #pragma unroll
            for (int sh = 1; sh <= 2; sh <<= 1) {
                ull o1 = __shfl_xor_sync(0xffffffffu, b1, sh);
                ull o2 = __shfl_xor_sync(0xffffffffu, b2, sh);
                ull n1 = umax(b1, o1);
                ull n2 = umax(umin(b1, o1), umax(b2, o2));
                b1 = n1; b2 = n2;
            }
            if ((lane & 3) == 0) {
                sred[(m_local * 2 + wn) * 2 + 0] = b1;
                sred[(m_local * 2 + wn) * 2 + 1] = b2;
            }
        }
    }
    __syncthreads();
    {
        const int row = tid;   // 128 rows, 128 threads
        ull p1a = sred[(row * 2 + 0) * 2 + 0], p2a = sred[(row * 2 + 0) * 2 + 1];
        ull p1b = sred[(row * 2 + 1) * 2 + 0], p2b = sred[(row * 2 + 1) * 2 + 1];
        ull b1 = umax(p1a, p1b);
        ull b2 = umax(umin(p1a, p1b), umax(p2a, p2b));
        g_top1[(ull)(m0 + row) * NSPLITS + nblk] = b1;   // [token][split]
        g_top2[(ull)(m0 + row) * NSPLITS + nblk] = b2;
    }
}

// ---------------------------------------------------------------------------
// K2a: warp-per-token split merge + near-tie exact fp32 fixup (lane-parallel)
// ---------------------------------------------------------------------------
__global__ void k_assign(const float* __restrict__ z, const float* __restrict__ E,
                         float* __restrict__ out) {
    const int gtid = blockIdx.x * 256 + threadIdx.x;
    const int n    = gtid >> 5;          // token = warp
    const int lane = gtid & 31;
    if (n >= NTOK) return;

    const ull* t1p = g_top1 + (ull)n * NSPLITS;
    const ull* t2p = g_top2 + (ull)n * NSPLITS;
    ull b1 = 0ull, b2 = 0ull;
    #pragma unroll
    for (int r = 0; r < 2; r++) {
        int s = lane + r * 32;
        ull t1 = t1p[s], t2 = t2p[s];
        if (t1 > b1)      { b2 = b1; b1 = t1; }
        else if (t1 > b2) { b2 = t1; }
        if (t2 > b2)      { b2 = t2; }
    }
    #pragma unroll
    for (int sh = 16; sh >= 1; sh >>= 1) {
        ull o1 = __shfl_xor_sync(0xffffffffu, b1, sh);
        ull o2 = __shfl_xor_sync(0xffffffffu, b2, sh);
        ull n1 = umax(b1, o1);
        ull n2 = umax(umin(b1, o1), umax(b2, o2));
        b1 = n1; b2 = n2;
    }

    int i1 = (KCODES - 1) - (int)(uint)(b1 & 0xffffffffu);
    int i2 = (KCODES - 1) - (int)(uint)(b2 & 0xffffffffu);
    uint m1 = ~(uint)(b1 >> 32), m2 = ~(uint)(b2 >> 32);
    float d1 = __uint_as_float((m1 & 0x80000000u) ? (m1 & 0x7fffffffu) : ~m1);
    float d2 = __uint_as_float((m2 & 0x80000000u) ? (m2 & 0x7fffffffu) : ~m2);

    int idx = i1;
    if (d2 - d1 < 2e-4f) {
        // exact fp32 re-score, lane-parallel (8 dims/lane), bucketed like ref
        int b = n >> 10, hw = n & 1023;
        const float* zp  = z + b * DD * HW + hw;
        const float* ep1 = E + i1;
        const float* ep2 = E + i2;
        float dot1 = 0.0f, dot2 = 0.0f;
        #pragma unroll
        for (int t = 0; t < 8; t++) {
            int d = t * 32 + lane;
            float zv = zp[d * HW];
            dot1 = fmaf(zv, ep1[d * KCODES], dot1);
            dot2 = fmaf(zv, ep2[d * KCODES], dot2);
        }
        #pragma unroll
        for (int sh = 16; sh >= 1; sh >>= 1) {
            dot1 += __shfl_xor_sync(0xffffffffu, dot1, sh);
            dot2 += __shfl_xor_sync(0xffffffffu, dot2, sh);
        }
        float sx2 = g_sx2[n];
        float e1  = (sx2 - 2.0f * dot1) + g_e2[i1];
        float e2x = (sx2 - 2.0f * dot2) + g_e2[i2];
        if (e2x < e1 || (e2x == e1 && i2 < i1)) idx = i2;
    }
    if (lane == 0) {
        g_idx[n] = idx;
        out[OUT_IDX + n] = (float)idx;
        atomicAdd(&out[OUT_CS + idx], 1.0f);
    }
}

// ---------------------------------------------------------------------------
// K2b: gather quantized (NCHW), scatter dw, accumulate loss
// ---------------------------------------------------------------------------
__global__ void k_scatter(const float* __restrict__ z, const float* __restrict__ E,
                          float* __restrict__ out) {
    int tx = threadIdx.x & 31;
    int ty = threadIdx.x >> 5;
    int hw = blockIdx.x * 32 + tx;
    int d  = blockIdx.y * 8 + ty;
    int b  = blockIdx.z;

    int n   = b * HW + hw;
    int idx = g_idx[n];
    float q  = E[d * KCODES + idx];
    int   zi = (b * DD + d) * HW + hw;
    float zv = z[zi];
    out[OUT_Q + zi] = q;
    float diff = q - zv;
    atomicAdd(&out[OUT_DW + d * KCODES + idx], zv);

    __shared__ float red[256];
    red[threadIdx.x] = diff * diff;
    __syncthreads();
    #pragma unroll
    for (int s = 128; s > 0; s >>= 1) {
        if (threadIdx.x < s) red[threadIdx.x] += red[threadIdx.x + s];
        __syncthreads();
    }
    if (threadIdx.x == 0) atomicAdd(&g_loss, (double)red[0]);
}

// ---------------------------------------------------------------------------
// K3: loss + perplexity
// ---------------------------------------------------------------------------
__global__ void k_final(float* __restrict__ out) {
    __shared__ float red[256];
    int t = threadIdx.x;
    float s = 0.0f;
    for (int k = t; k < KCODES; k += 256) {
        float p = out[OUT_CS + k] * (1.0f / 8192.0f);
        s += p * logf(p + 1e-10f);
    }
    red[t] = s;
    __syncthreads();
    #pragma unroll
    for (int st = 128; st > 0; st >>= 1) {
        if (t < st) red[t] += red[t + st];
        __syncthreads();
    }
    if (t == 0) {
        out[OUT_PERP] = expf(-red[0]);
        out[OUT_LOSS] = (float)(0.25 * g_loss / 2097152.0);
    }
}

// ---------------------------------------------------------------------------
extern "C" void kernel_launch(void* const* d_in, const int* in_sizes, int n_in,
                              void* d_out, int out_size) {
    const float* z = (const float*)d_in[0];         // [8,256,32,32]
    const float* E = (const float*)d_in[1];         // [256,8192]
    float* out = (float*)d_out;

    cudaFuncSetAttribute(k_mma, cudaFuncAttributeMaxDynamicSharedMemorySize,
                         SMEM_DYN);

    k_prep   <<< 512, 256 >>>(z, E, out);
    k_mma    <<< dim3(NTOK / MTILE, NSPLITS), 128, SMEM_DYN >>>();
    k_assign <<< (NTOK * 32) / 256, 256 >>>(z, E, out);
    k_scatter<<< dim3(HW / 32, DD / 8, BATCH), 256 >>>(z, E, out);
    k_final  <<< 1, 256 >>>(out);
}